// round 10
// baseline (speedup 1.0000x reference)
#include <cuda_runtime.h>
#include <cstdint>

#define NN 50000
#define NE 800000
typedef unsigned long long ull;

// ---------------- scratch -----------------------------------------------
__device__ __align__(128) float    g_Y1[3 * NE];
__device__ __align__(128) float    g_h1[(size_t)64 * NE];
__device__ __align__(128) float    g_hmid[(size_t)64 * NE];
__device__ __align__(128) float    g_acc0[(size_t)NN * 64];
__device__ __align__(128) float    g_acc1[(size_t)NN * 192];
__device__ __align__(128) float    g_f0[(size_t)NN * 64];
__device__ __align__(128) float    g_f1[(size_t)NN * 192];
__device__ __align__(128) float    g_msg0[(size_t)64 * NE];
__device__ __align__(128) float    g_msg1[(size_t)192 * NE];
__device__ __align__(128) float    g_a[(size_t)8 * NE];
__device__ __align__(128) unsigned g_amax[(size_t)NN * 8];
__device__ __align__(128) float    g_z[(size_t)NN * 8];
__device__ __align__(128) float    g_agg0[(size_t)NN * 64];
__device__ __align__(128) float    g_agg1[(size_t)NN * 192];
__device__ __align__(128) float    g_mid[(size_t)NN * 64];
__device__ __align__(128) float    g_gateT[(size_t)64 * NN];

// ---------------- helpers ------------------------------------------------
__device__ __forceinline__ void red4(float* p, float a, float b, float c, float d) {
    asm volatile("red.global.add.v4.f32 [%0], {%1,%2,%3,%4};"
                 :: "l"(p), "f"(a), "f"(b), "f"(c), "f"(d) : "memory");
}
__device__ __forceinline__ unsigned fkey(float x) {
    unsigned u = __float_as_uint(x);
    return (u & 0x80000000u) ? ~u : (u | 0x80000000u);
}
__device__ __forceinline__ float fdec(unsigned k) {
    return (k & 0x80000000u) ? __uint_as_float(k & 0x7FFFFFFFu) : __uint_as_float(~k);
}
__device__ __forceinline__ float sigf(float x) { return __fdividef(1.f, 1.f + __expf(-x)); }
__device__ __forceinline__ float siluf(float x) { return x * sigf(x); }

__device__ __forceinline__ ull pack2(float a) {
    ull r; unsigned u = __float_as_uint(a);
    asm("mov.b64 %0,{%1,%1};" : "=l"(r) : "r"(u));
    return r;
}
#define FMA2(acc, a, b) asm("fma.rn.f32x2 %0,%1,%2,%0;" : "+l"(acc) : "l"(a), "l"(b))
__device__ __forceinline__ float2 unpack2(ull v) {
    unsigned lo, hi;
    asm("mov.b64 {%0,%1},%2;" : "=r"(lo), "=r"(hi) : "l"(v));
    return make_float2(__uint_as_float(lo), __uint_as_float(hi));
}

// 64-output GEMV for ONE node. x in smem column sx[c*BT+tid].
template<int NCH, int LDW, int BT>
__device__ __forceinline__ void gemv_s(const float* __restrict__ sW,
                                       const float* __restrict__ sx, int tid,
                                       ull* __restrict__ y) {
#pragma unroll 1
    for (int c0 = 0; c0 < NCH; c0++) {
        const float* xp = sx + (c0 * 8) * BT + tid;
        const float* wb = sW + (c0 * 8) * LDW;
        float xc[8];
#pragma unroll
        for (int i = 0; i < 8; i++) xc[i] = xp[i * BT];
#pragma unroll
        for (int i = 0; i < 8; i++) {
            ull xx = pack2(xc[i]);
            const ulonglong2* wp = (const ulonglong2*)(wb + i * LDW);
#pragma unroll
            for (int d = 0; d < 16; d++) {
                ulonglong2 w = wp[d];
                FMA2(y[2*d],   xx, w.x);
                FMA2(y[2*d+1], xx, w.y);
            }
        }
    }
}

// 32-output GEMV for TWO ADJACENT edges; x streamed from gmem (L2-hot) via
// LDG.64, double-buffered. sW row-major LDW, 32 consecutive output columns.
template<int LDW>
__device__ __forceinline__ void gemv2g(const float* __restrict__ sW,
                                       const float* __restrict__ gx,  // + e0
                                       ull* __restrict__ y0, ull* __restrict__ y1) {
    float2 xc[8], xn[8];
#pragma unroll
    for (int i = 0; i < 8; i++) xc[i] = *(const float2*)(gx + (size_t)i * NE);
#pragma unroll 1
    for (int c0 = 0; c0 < 8; c0++) {
        if (c0 < 7) {
#pragma unroll
            for (int i = 0; i < 8; i++)
                xn[i] = *(const float2*)(gx + (size_t)((c0+1)*8 + i) * NE);
        }
#pragma unroll
        for (int j = 0; j < 8; j++) {
            ull x0 = pack2(xc[j].x), x1 = pack2(xc[j].y);
            const ulonglong2* wp = (const ulonglong2*)(sW + (c0*8 + j) * LDW);
#pragma unroll
            for (int d = 0; d < 8; d++) {
                ulonglong2 w = wp[d];
                FMA2(y0[2*d],   x0, w.x); FMA2(y0[2*d+1], x0, w.y);
                FMA2(y1[2*d],   x1, w.x); FMA2(y1[2*d+1], x1, w.y);
            }
        }
#pragma unroll
        for (int i = 0; i < 8; i++) xc[i] = xn[i];
    }
}
__device__ __forceinline__ void initp16(ull* y, const float* b) {
#pragma unroll
    for (int i = 0; i < 16; i++) y[i] = *(const ull*)(b + 2*i);
}
__device__ __forceinline__ void zerop(ull* y) {
#pragma unroll
    for (int i = 0; i < 32; i++) y[i] = 0ull;
}

// ---------------- K0: zero ----------------------------------------------
__global__ void k_zero() {
    int t = blockIdx.x * blockDim.x + threadIdx.x, s = gridDim.x * blockDim.x;
    for (int i = t; i < NN * 64;  i += s) { g_acc0[i] = 0.f; g_agg0[i] = 0.f; }
    for (int i = t; i < NN * 192; i += s) { g_acc1[i] = 0.f; g_agg1[i] = 0.f; }
    for (int i = t; i < NN * 8;   i += s) { g_z[i] = 0.f; g_amax[i] = 0u; }
}

// ---------------- K1: edge RBF + MLP + degree scatter ---------------------
__global__ void __launch_bounds__(256, 2) k_edge_deg(
    const float* __restrict__ pos, const float* __restrict__ exp_w,
    const float* __restrict__ W1, const float* __restrict__ b1,
    const float* __restrict__ W2, const float* __restrict__ b2,
    const float* __restrict__ Wdeg, const float* __restrict__ bdeg,
    const int* __restrict__ esrc, const int* __restrict__ edst)
{
    extern __shared__ float sm[];
    float* sW1 = sm;            // 3584 (rows 50..55 zero)
    float* sW2 = sW1 + 3584;    // 4096
    float* sWd = sW2 + 4096;    // 8192
    float* sb1 = sWd + 8192;    // 64
    float* sb2 = sb1 + 64;      // 64
    float* sbd = sb2 + 64;      // 128
    float* sew = sbd + 128;     // 64
    for (int i = threadIdx.x; i < 3584; i += 256) sW1[i] = (i < 3200) ? W1[i] : 0.f;
    for (int i = threadIdx.x; i < 4096; i += 256) sW2[i] = W2[i];
    for (int i = threadIdx.x; i < 8192; i += 256) sWd[i] = Wdeg[i];
    if (threadIdx.x < 64) { sb1[threadIdx.x] = b1[threadIdx.x];
                            sb2[threadIdx.x] = b2[threadIdx.x];
                            sew[threadIdx.x] = exp_w[threadIdx.x]; }
    if (threadIdx.x < 128) sbd[threadIdx.x] = bdeg[threadIdx.x];
    __syncthreads();

    int tid = threadIdx.x;
    int e0 = blockIdx.x * 512 + 2 * tid;
    if (e0 >= NE) return;
    int2 ss = *(const int2*)&esrc[e0];
    int2 dd = *(const int2*)&edst[e0];
    int s0 = ss.x, s1 = ss.y, d0 = dd.x, d1 = dd.y;

    float y00, y01, y02, ed0, cut0, y10, y11, y12, ed1, cut1;
    {
        float dx = pos[3*d0]-pos[3*s0], dy = pos[3*d0+1]-pos[3*s0+1], dz = pos[3*d0+2]-pos[3*s0+2];
        float dist = sqrtf(dx*dx + dy*dy + dz*dz + 1e-9f);
        float ri = __fdividef(1.f, dist);
        y00 = dx*ri; y01 = dy*ri; y02 = dz*ri;
        cut0 = (dist < 5.f) ? 0.5f * (__cosf(0.6283185307179586f * dist) + 1.f) : 0.f;
        ed0 = __expf(-dist);
    }
    {
        float dx = pos[3*d1]-pos[3*s1], dy = pos[3*d1+1]-pos[3*s1+1], dz = pos[3*d1+2]-pos[3*s1+2];
        float dist = sqrtf(dx*dx + dy*dy + dz*dz + 1e-9f);
        float ri = __fdividef(1.f, dist);
        y10 = dx*ri; y11 = dy*ri; y12 = dz*ri;
        cut1 = (dist < 5.f) ? 0.5f * (__cosf(0.6283185307179586f * dist) + 1.f) : 0.f;
        ed1 = __expf(-dist);
    }
    *(float2*)&g_Y1[e0]      = make_float2(y00, y10);
    *(float2*)&g_Y1[NE+e0]   = make_float2(y01, y11);
    *(float2*)&g_Y1[2*NE+e0] = make_float2(y02, y12);

    const float startc = 0.006737946999085467f;
    const float stepc  = (1.f - startc) / 49.f;
    const float bbq    = 0.04f * (1.f - startc);
    const float beta   = 1.f / (bbq * bbq);

    ull a0[16], a1[16];
    // ---- stage 1: rbf @ W1 -> h1 (gmem) ----
#pragma unroll 1
    for (int ch = 0; ch < 2; ch++) {
        initp16(a0, sb1 + ch*32); initp16(a1, sb1 + ch*32);
        const float* wbase = sW1 + ch*32;
#pragma unroll 1
        for (int c0 = 0; c0 < 7; c0++) {
            float xa[8], xb[8];
#pragma unroll
            for (int j = 0; j < 8; j++) {
                int i = c0*8 + j;
                float mi = startc + stepc * (float)i;
                float t0v = ed0 - mi, t1v = ed1 - mi;
                xa[j] = cut0 * __expf(-beta * t0v * t0v);
                xb[j] = cut1 * __expf(-beta * t1v * t1v);
            }
#pragma unroll
            for (int j = 0; j < 8; j++) {
                ull x0 = pack2(xa[j]), x1 = pack2(xb[j]);
                const ulonglong2* wp = (const ulonglong2*)(wbase + (c0*8 + j)*64);
#pragma unroll
                for (int d = 0; d < 8; d++) {
                    ulonglong2 w = wp[d];
                    FMA2(a0[2*d], x0, w.x); FMA2(a0[2*d+1], x0, w.y);
                    FMA2(a1[2*d], x1, w.x); FMA2(a1[2*d+1], x1, w.y);
                }
            }
        }
#pragma unroll
        for (int i = 0; i < 16; i++) {
            float2 u = unpack2(a0[i]), v = unpack2(a1[i]);
            int r = ch*32 + 2*i;
            *(float2*)&g_h1[(size_t)r*NE + e0]     = make_float2(siluf(u.x), siluf(v.x));
            *(float2*)&g_h1[(size_t)(r+1)*NE + e0] = make_float2(siluf(u.y), siluf(v.y));
        }
    }
    // ---- stage 2: h1 @ W2 -> h2 (g_hmid) ----
#pragma unroll 1
    for (int ch = 0; ch < 2; ch++) {
        initp16(a0, sb2 + ch*32); initp16(a1, sb2 + ch*32);
        gemv2g<64>(sW2 + ch*32, g_h1 + e0, a0, a1);
#pragma unroll
        for (int i = 0; i < 16; i++) {
            float2 u = unpack2(a0[i]), v = unpack2(a1[i]);
            int r = ch*32 + 2*i;
            *(float2*)&g_hmid[(size_t)r*NE + e0]     = make_float2(siluf(u.x), siluf(v.x));
            *(float2*)&g_hmid[(size_t)(r+1)*NE + e0] = make_float2(siluf(u.y), siluf(v.y));
        }
    }
    // ---- stage 3: wd0 scatter ----
#pragma unroll 1
    for (int ch = 0; ch < 2; ch++) {
        initp16(a0, sbd + ch*32); initp16(a1, sbd + ch*32);
        gemv2g<128>(sWd + ch*32, g_hmid + e0, a0, a1);
#pragma unroll
        for (int q = 0; q < 8; q++) {
            int c = ch*32 + 4*q;
            float2 p0 = unpack2(a0[2*q]), p1 = unpack2(a0[2*q+1]);
            red4(&g_acc0[d0*64 + c], p0.x*sew[c], p0.y*sew[c+1], p1.x*sew[c+2], p1.y*sew[c+3]);
            float2 q0 = unpack2(a1[2*q]), q1 = unpack2(a1[2*q+1]);
            red4(&g_acc0[d1*64 + c], q0.x*sew[c], q0.y*sew[c+1], q1.x*sew[c+2], q1.y*sew[c+3]);
        }
    }
    // ---- stage 4: wd1 scatter (outer with Y1) ----
#pragma unroll 1
    for (int ch = 0; ch < 2; ch++) {
        initp16(a0, sbd + 64 + ch*32); initp16(a1, sbd + 64 + ch*32);
        gemv2g<128>(sWd + 64 + ch*32, g_hmid + e0, a0, a1);
#pragma unroll
        for (int q = 0; q < 8; q++) {
            int c = ch*32 + 4*q;
            float2 p0 = unpack2(a0[2*q]), p1 = unpack2(a0[2*q+1]);
            float w0 = p0.x*sew[c], w1 = p0.y*sew[c+1], w2 = p1.x*sew[c+2], w3 = p1.y*sew[c+3];
#pragma unroll
            for (int i = 0; i < 3; i++) {
                float yi = (i == 0) ? y00 : ((i == 1) ? y01 : y02);
                red4(&g_acc1[(size_t)d0*192 + i*64 + c], w0*yi, w1*yi, w2*yi, w3*yi);
            }
            float2 q0 = unpack2(a1[2*q]), q1 = unpack2(a1[2*q+1]);
            float u0 = q0.x*sew[c], u1 = q0.y*sew[c+1], u2 = q1.x*sew[c+2], u3 = q1.y*sew[c+3];
#pragma unroll
            for (int i = 0; i < 3; i++) {
                float yi = (i == 0) ? y10 : ((i == 1) ? y11 : y12);
                red4(&g_acc1[(size_t)d1*192 + i*64 + c], u0*yi, u1*yi, u2*yi, u3*yi);
            }
        }
    }
}

// ---------------- K2: node embed + deg proj ------------------------------
__global__ void __launch_bounds__(128) k_node_deg(
    const float* __restrict__ embed_W, const float* __restrict__ P0,
    const float* __restrict__ P1, const int* __restrict__ atom)
{
    extern __shared__ float sm[];
    float* sP0 = sm; float* sP1 = sP0 + 4096; float* sx = sP1 + 4096;
    for (int i = threadIdx.x; i < 4096; i += 128) { sP0[i] = P0[i]; sP1[i] = P1[i]; }
    __syncthreads();
    int tid = threadIdx.x;
    int n = blockIdx.x * 128 + tid;
    if (n >= NN) return;
    int at = atom[n];
    ull acc[32];
#pragma unroll
    for (int g = 0; g < 16; g++) { float4 v = ((const float4*)(g_acc0 + n*64))[g];
        sx[(4*g)*128+tid]=v.x; sx[(4*g+1)*128+tid]=v.y; sx[(4*g+2)*128+tid]=v.z; sx[(4*g+3)*128+tid]=v.w; }
    zerop(acc);
    gemv_s<8, 64, 128>(sP0, sx, tid, acc);
#pragma unroll
    for (int i = 0; i < 32; i++) { float2 v = unpack2(acc[i]);
        g_f0[n*64 + 2*i]   = embed_W[at*64 + 2*i]   + 0.25f * v.x;
        g_f0[n*64 + 2*i+1] = embed_W[at*64 + 2*i+1] + 0.25f * v.y; }
#pragma unroll 1
    for (int i = 0; i < 3; i++) {
#pragma unroll
        for (int g = 0; g < 16; g++) { float4 v = ((const float4*)(g_acc1 + (size_t)n*192 + i*64))[g];
            sx[(4*g)*128+tid]=v.x; sx[(4*g+1)*128+tid]=v.y; sx[(4*g+2)*128+tid]=v.z; sx[(4*g+3)*128+tid]=v.w; }
        zerop(acc);
        gemv_s<8, 64, 128>(sP1, sx, tid, acc);
#pragma unroll
        for (int j = 0; j < 32; j++) { float2 v = unpack2(acc[j]);
            g_f1[(size_t)n*192 + i*64 + 2*j]   = 0.25f * v.x;
            g_f1[(size_t)n*192 + i*64 + 2*j+1] = 0.25f * v.y; }
    }
}

// ---------------- K3: edge attention (adjacent pair, pipelined gathers) ---
__global__ void __launch_bounds__(256, 2) k_edge_attn(
    const float* __restrict__ Wattn, const float* __restrict__ battn,
    const float* __restrict__ alpha_dot,
    const int* __restrict__ esrc, const int* __restrict__ edst)
{
    extern __shared__ float sm[];
    float* sW  = sm;                // 20480
    float* sb  = sW + 20480;        // 320
    float* sad = sb + 320;          // 64
    for (int i = threadIdx.x; i < 20480; i += 256) sW[i] = Wattn[i];
    for (int i = threadIdx.x; i < 320; i += 256) sb[i] = battn[i];
    if (threadIdx.x < 64) sad[threadIdx.x] = alpha_dot[threadIdx.x];
    __syncthreads();

    int tid = threadIdx.x;
    int e0 = blockIdx.x * 512 + 2 * tid;
    if (e0 >= NE) return;
    int2 ss = *(const int2*)&esrc[e0];
    int2 dd = *(const int2*)&edst[e0];
    int s0 = ss.x, s1 = ss.y, d0 = dd.x, d1 = dd.y;
    float2 yv0 = *(const float2*)&g_Y1[e0];
    float2 yv1 = *(const float2*)&g_Y1[NE+e0];
    float2 yv2 = *(const float2*)&g_Y1[2*NE+e0];
    float y00 = yv0.x, y01 = yv1.x, y02 = yv2.x;
    float y10 = yv0.y, y11 = yv1.y, y12 = yv2.y;

    const float4* f0p0 = (const float4*)(g_f0 + (size_t)s0*64);
    const float4* f1p0 = (const float4*)(g_f1 + (size_t)s0*192);
    const float4* f0p1 = (const float4*)(g_f0 + (size_t)s1*64);
    const float4* f1p1 = (const float4*)(g_f1 + (size_t)s1*192);
    const float is3 = 0.5773502691896258f, is2 = 0.7071067811865476f;
    float hsum0 = 0.f, hsum1 = 0.f;

    // prefetch gathers for g=0 (consumed after the first mainloop)
    float4 P00 = f0p0[0], Pa0 = f1p0[0], Pb0 = f1p0[16], Pc0 = f1p0[32];
    float4 P01 = f0p1[0], Pa1 = f1p1[0], Pb1 = f1p1[16], Pc1 = f1p1[32];

#pragma unroll 1
    for (int g = 0; g < 16; g++) {
        ull acc0[5][2], acc1[5][2];
#pragma unroll
        for (int q = 0; q < 5; q++) {
            ull b0 = *(const ull*)(sb + q*64 + 4*g);
            ull b1 = *(const ull*)(sb + q*64 + 4*g + 2);
            acc0[q][0] = b0; acc0[q][1] = b1;
            acc1[q][0] = b0; acc1[q][1] = b1;
        }
        float2 xc[8], xn[8];
#pragma unroll
        for (int i = 0; i < 8; i++) xc[i] = *(const float2*)(g_hmid + (size_t)i*NE + e0);
#pragma unroll 1
        for (int k0 = 0; k0 < 8; k0++) {
            if (k0 < 7) {
#pragma unroll
                for (int i = 0; i < 8; i++)
                    xn[i] = *(const float2*)(g_hmid + (size_t)((k0+1)*8 + i)*NE + e0);
            }
#pragma unroll
            for (int i = 0; i < 8; i++) {
                ull x0 = pack2(xc[i].x), x1 = pack2(xc[i].y);
                const float* wb = sW + (k0*8 + i)*320 + 4*g;
#pragma unroll
                for (int q = 0; q < 5; q++) {
                    ulonglong2 w = *(const ulonglong2*)(wb + q*64);
                    FMA2(acc0[q][0], x0, w.x); FMA2(acc0[q][1], x0, w.y);
                    FMA2(acc1[q][0], x1, w.x); FMA2(acc1[q][1], x1, w.y);
                }
            }
#pragma unroll
            for (int i = 0; i < 8; i++) xc[i] = xn[i];
        }
        // ---- epilogue (both edges), consuming prefetched gathers ----
        float wq0[5][4], wq1[5][4];
#pragma unroll
        for (int q = 0; q < 5; q++) {
            float2 a = unpack2(acc0[q][0]), b = unpack2(acc0[q][1]);
            wq0[q][0] = a.x; wq0[q][1] = a.y; wq0[q][2] = b.x; wq0[q][3] = b.y;
            float2 c = unpack2(acc1[q][0]), d = unpack2(acc1[q][1]);
            wq1[q][0] = c.x; wq1[q][1] = c.y; wq1[q][2] = d.x; wq1[q][3] = d.y;
        }
        float s0v0[4] = {P00.x,P00.y,P00.z,P00.w};
        float a0v0[4] = {Pa0.x,Pa0.y,Pa0.z,Pa0.w};
        float a1v0[4] = {Pb0.x,Pb0.y,Pb0.z,Pb0.w};
        float a2v0[4] = {Pc0.x,Pc0.y,Pc0.z,Pc0.w};
        float s0v1[4] = {P01.x,P01.y,P01.z,P01.w};
        float a0v1[4] = {Pa1.x,Pa1.y,Pa1.z,Pa1.w};
        float a1v1[4] = {Pb1.x,Pb1.y,Pb1.z,Pb1.w};
        float a2v1[4] = {Pc1.x,Pc1.y,Pc1.z,Pc1.w};
#pragma unroll
        for (int u = 0; u < 4; u++) {
            int c = 4*g + u;
            float m00, m10a, m11a, m12a;
            {
                float w0 = wq0[0][u], w1 = wq0[1][u], w2 = wq0[2][u], w3 = wq0[3][u], w4 = wq0[4][u];
                float s0c = s0v0[u], a0 = a0v0[u], a1 = a1v0[u], a2 = a2v0[u];
                float dot = a0*y00 + a1*y01 + a2*y02;
                m00 = w0*s0c + w3*dot*is3;
                float cx = a1*y02 - a2*y01, cy = a2*y00 - a0*y02, cz = a0*y01 - a1*y00;
                m10a = w1*s0c*y00 + w2*a0 + w4*cx*is2;
                m11a = w1*s0c*y01 + w2*a1 + w4*cy*is2;
                m12a = w1*s0c*y02 + w2*a2 + w4*cz*is2;
                hsum0 += (0.2f*m00 + 0.8f*m00*sigf(m00)) * sad[c];
            }
            float m01, m10b, m11b, m12b;
            {
                float w0 = wq1[0][u], w1 = wq1[1][u], w2 = wq1[2][u], w3 = wq1[3][u], w4 = wq1[4][u];
                float s0c = s0v1[u], a0 = a0v1[u], a1 = a1v1[u], a2 = a2v1[u];
                float dot = a0*y10 + a1*y11 + a2*y12;
                m01 = w0*s0c + w3*dot*is3;
                float cx = a1*y12 - a2*y11, cy = a2*y10 - a0*y12, cz = a0*y11 - a1*y10;
                m10b = w1*s0c*y10 + w2*a0 + w4*cx*is2;
                m11b = w1*s0c*y11 + w2*a1 + w4*cy*is2;
                m12b = w1*s0c*y12 + w2*a2 + w4*cz*is2;
                hsum1 += (0.2f*m01 + 0.8f*m01*sigf(m01)) * sad[c];
            }
            *(float2*)&g_msg0[(size_t)c*NE + e0]          = make_float2(m00, m01);
            *(float2*)&g_msg1[(size_t)(0*64+c)*NE + e0]   = make_float2(m10a, m10b);
            *(float2*)&g_msg1[(size_t)(1*64+c)*NE + e0]   = make_float2(m11a, m11b);
            *(float2*)&g_msg1[(size_t)(2*64+c)*NE + e0]   = make_float2(m12a, m12b);
        }
        if (g & 1) {
            int hh = g >> 1;
            *(float2*)&g_a[(size_t)hh*NE + e0] = make_float2(hsum0, hsum1);
            atomicMax(&g_amax[d0*8 + hh], fkey(hsum0));
            atomicMax(&g_amax[d1*8 + hh], fkey(hsum1));
            hsum0 = 0.f; hsum1 = 0.f;
        }
        // issue next g's gathers NOW; latency covered by next mainloop
        if (g < 15) {
            P00 = f0p0[g+1]; Pa0 = f1p0[g+1]; Pb0 = f1p0[17+g]; Pc0 = f1p0[33+g];
            P01 = f0p1[g+1]; Pa1 = f1p1[g+1]; Pb1 = f1p1[17+g]; Pc1 = f1p1[33+g];
        }
    }
}

// ---------------- K4: ea + z scatter + aggregation (fused, 2 edges) ------
__global__ void __launch_bounds__(256) k_edge_agg(const int* __restrict__ edst) {
    int tid = threadIdx.x;
    int e0 = blockIdx.x * 512 + 2 * tid;
    if (e0 >= NE) return;
    int2 dd = *(const int2*)&edst[e0];
    int d0 = dd.x, d1 = dd.y;
    float2 ea[8];
#pragma unroll
    for (int h = 0; h < 8; h++) {
        float2 a = *(const float2*)&g_a[(size_t)h*NE + e0];
        ea[h].x = __expf(a.x - fdec(g_amax[d0*8 + h]));
        ea[h].y = __expf(a.y - fdec(g_amax[d1*8 + h]));
    }
    red4(&g_z[d0*8],     ea[0].x, ea[1].x, ea[2].x, ea[3].x);
    red4(&g_z[d0*8 + 4], ea[4].x, ea[5].x, ea[6].x, ea[7].x);
    red4(&g_z[d1*8],     ea[0].y, ea[1].y, ea[2].y, ea[3].y);
    red4(&g_z[d1*8 + 4], ea[4].y, ea[5].y, ea[6].y, ea[7].y);
#pragma unroll
    for (int g = 0; g < 16; g++) {
        float2 w = ea[g >> 1];
        float2 m0 = *(const float2*)&g_msg0[(size_t)(4*g)*NE + e0];
        float2 m1 = *(const float2*)&g_msg0[(size_t)(4*g+1)*NE + e0];
        float2 m2 = *(const float2*)&g_msg0[(size_t)(4*g+2)*NE + e0];
        float2 m3 = *(const float2*)&g_msg0[(size_t)(4*g+3)*NE + e0];
        red4(&g_agg0[d0*64 + 4*g], m0.x*w.x, m1.x*w.x, m2.x*w.x, m3.x*w.x);
        red4(&g_agg0[d1*64 + 4*g], m0.y*w.y, m1.y*w.y, m2.y*w.y, m3.y*w.y);
#pragma unroll
        for (int i = 0; i < 3; i++) {
            float2 u0 = *(const float2*)&g_msg1[(size_t)(i*64 + 4*g)*NE + e0];
            float2 u1 = *(const float2*)&g_msg1[(size_t)(i*64 + 4*g+1)*NE + e0];
            float2 u2 = *(const float2*)&g_msg1[(size_t)(i*64 + 4*g+2)*NE + e0];
            float2 u3 = *(const float2*)&g_msg1[(size_t)(i*64 + 4*g+3)*NE + e0];
            red4(&g_agg1[(size_t)d0*192 + i*64 + 4*g], u0.x*w.x, u1.x*w.x, u2.x*w.x, u3.x*w.x);
            red4(&g_agg1[(size_t)d1*192 + i*64 + 4*g], u0.y*w.y, u1.y*w.y, u2.y*w.y, u3.y*w.y);
        }
    }
}

// ---------------- K6: node out_proj + FFN part A -------------------------
__global__ void __launch_bounds__(128) k_node_postA(
    const float* __restrict__ P0, const float* __restrict__ P1,
    const float* __restrict__ W1s, const float* __restrict__ b1s)
{
    extern __shared__ float sm[];
    float* sP0 = sm; float* sP1 = sP0 + 4096; float* sWs = sP1 + 4096;
    float* sbs = sWs + 8192; float* sx = sbs + 128;
    for (int i = threadIdx.x; i < 4096; i += 128) { sP0[i] = P0[i]; sP1[i] = P1[i]; }
    for (int i = threadIdx.x; i < 8192; i += 128) sWs[i] = W1s[i];
    if (threadIdx.x < 128) sbs[threadIdx.x] = b1s[threadIdx.x];
    __syncthreads();
    int tid = threadIdx.x;
    int n = blockIdx.x * 128 + tid;
    if (n >= NN) return;
    float rz[8];
#pragma unroll
    for (int h = 0; h < 8; h++) {
        float z = g_z[n*8 + h];
        rz[h] = (z > 0.f) ? __fdividef(1.f, z) : 0.f;
    }
    ull acc[32];
#pragma unroll
    for (int g = 0; g < 16; g++) { float4 v = ((const float4*)(g_agg0 + n*64))[g];
        float r = rz[g >> 1];
        sx[(4*g)*128+tid]=v.x*r; sx[(4*g+1)*128+tid]=v.y*r;
        sx[(4*g+2)*128+tid]=v.z*r; sx[(4*g+3)*128+tid]=v.w*r; }
    zerop(acc);
    gemv_s<8, 64, 128>(sP0, sx, tid, acc);
    float x[64];
#pragma unroll
    for (int i = 0; i < 32; i++) { float2 v = unpack2(acc[i]);
        float a = g_f0[n*64 + 2*i] + v.x, b = g_f0[n*64 + 2*i+1] + v.y;
        x[2*i] = a; x[2*i+1] = b;
        g_f0[n*64 + 2*i] = a; g_f0[n*64 + 2*i+1] = b;
        sx[(2*i)*128+tid] = a; sx[(2*i+1)*128+tid] = b; }
    zerop(acc);
    gemv_s<8, 128, 128>(sWs, sx, tid, acc);
#pragma unroll
    for (int i = 0; i < 32; i++) { float2 v = unpack2(acc[i]);
        g_mid[n*64 + 2*i]   = siluf(v.x + sbs[2*i]);
        g_mid[n*64 + 2*i+1] = siluf(v.y + sbs[2*i+1]); }
    zerop(acc);
    gemv_s<8, 128, 128>(sWs + 64, sx, tid, acc);
#pragma unroll
    for (int i = 0; i < 32; i++) { float2 v = unpack2(acc[i]);
        g_gateT[(size_t)(2*i)*NN + n]   = sigf(v.x + sbs[64 + 2*i]);
        g_gateT[(size_t)(2*i+1)*NN + n] = sigf(v.y + sbs[64 + 2*i+1]); }
#pragma unroll 1
    for (int i = 0; i < 3; i++) {
#pragma unroll
        for (int g = 0; g < 16; g++) { float4 v = ((const float4*)(g_agg1 + (size_t)n*192 + i*64))[g];
            float r = rz[g >> 1];
            sx[(4*g)*128+tid]=v.x*r; sx[(4*g+1)*128+tid]=v.y*r;
            sx[(4*g+2)*128+tid]=v.z*r; sx[(4*g+3)*128+tid]=v.w*r; }
        zerop(acc);
        gemv_s<8, 64, 128>(sP1, sx, tid, acc);
#pragma unroll
        for (int j = 0; j < 32; j++) { float2 v = unpack2(acc[j]);
            g_f1[(size_t)n*192 + i*64 + 2*j]   += v.x;
            g_f1[(size_t)n*192 + i*64 + 2*j+1] += v.y; }
    }
}

// ---------------- K7: node FFN part B + output ---------------------------
__global__ void __launch_bounds__(128) k_node_postB(
    const float* __restrict__ W2s, const float* __restrict__ b2s,
    const float* __restrict__ W1v, const float* __restrict__ W2v,
    float* __restrict__ out)
{
    extern __shared__ float sm[];
    float* sWs = sm; float* sWa = sWs + 4096; float* sWb = sWa + 4096;
    float* sb2 = sWb + 4096; float* sx = sb2 + 64;
    for (int i = threadIdx.x; i < 4096; i += 128) { sWs[i] = W2s[i]; sWa[i] = W1v[i]; sWb[i] = W2v[i]; }
    if (threadIdx.x < 64) sb2[threadIdx.x] = b2s[threadIdx.x];
    __syncthreads();
    int tid = threadIdx.x;
    int n = blockIdx.x * 128 + tid;
    if (n >= NN) return;
    ull acc[32];
#pragma unroll
    for (int g = 0; g < 16; g++) { float4 v = ((const float4*)(g_mid + n*64))[g];
        sx[(4*g)*128+tid]=v.x; sx[(4*g+1)*128+tid]=v.y;
        sx[(4*g+2)*128+tid]=v.z; sx[(4*g+3)*128+tid]=v.w; }
    zerop(acc);
    gemv_s<8, 64, 128>(sWs, sx, tid, acc);
#pragma unroll
    for (int i = 0; i < 32; i++) { float2 v = unpack2(acc[i]);
        out[(size_t)n*256 + 2*i]   = g_f0[n*64 + 2*i]   + v.x + sb2[2*i];
        out[(size_t)n*256 + 2*i+1] = g_f0[n*64 + 2*i+1] + v.y + sb2[2*i+1]; }

    float gate[64];
#pragma unroll
    for (int j = 0; j < 64; j++) gate[j] = g_gateT[(size_t)j*NN + n];
#pragma unroll 1
    for (int i = 0; i < 3; i++) {
        float x[64];
#pragma unroll
        for (int g = 0; g < 16; g++) { float4 v = ((const float4*)(g_f1 + (size_t)n*192 + i*64))[g];
            x[4*g]=v.x; x[4*g+1]=v.y; x[4*g+2]=v.z; x[4*g+3]=v.w;
            sx[(4*g)*128+tid]=v.x; sx[(4*g+1)*128+tid]=v.y;
            sx[(4*g+2)*128+tid]=v.z; sx[(4*g+3)*128+tid]=v.w; }
        zerop(acc);
        gemv_s<8, 64, 128>(sWa, sx, tid, acc);
#pragma unroll
        for (int j = 0; j < 32; j++) { float2 v = unpack2(acc[j]);
            sx[(2*j)*128+tid]   = v.x * gate[2*j];
            sx[(2*j+1)*128+tid] = v.y * gate[2*j+1]; }
        zerop(acc);
        gemv_s<8, 64, 128>(sWb, sx, tid, acc);
#pragma unroll
        for (int j = 0; j < 32; j++) { float2 v = unpack2(acc[j]);
            out[(size_t)n*256 + 64 + (2*j)*3 + i]   = x[2*j]   + v.x;
            out[(size_t)n*256 + 64 + (2*j+1)*3 + i] = x[2*j+1] + v.y; }
    }
}

// ---------------- launch -------------------------------------------------
extern "C" void kernel_launch(void* const* d_in, const int* in_sizes, int n_in,
                              void* d_out, int out_size) {
    const float* pos     = (const float*)d_in[0];
    const float* embed_W = (const float*)d_in[1];
    const float* exp_w   = (const float*)d_in[2];
    const float* rW1     = (const float*)d_in[3];
    const float* rb1     = (const float*)d_in[4];
    const float* rW2     = (const float*)d_in[5];
    const float* rb2     = (const float*)d_in[6];
    const float* rWdeg   = (const float*)d_in[7];
    const float* rbdeg   = (const float*)d_in[8];
    const float* rWattn  = (const float*)d_in[9];
    const float* rbattn  = (const float*)d_in[10];
    const float* dp0     = (const float*)d_in[11];
    const float* dp1     = (const float*)d_in[12];
    const float* adot    = (const float*)d_in[13];
    const float* op0     = (const float*)d_in[14];
    const float* op1     = (const float*)d_in[15];
    const float* fW1s    = (const float*)d_in[16];
    const float* fb1s    = (const float*)d_in[17];
    const float* fW1v    = (const float*)d_in[18];
    const float* fW2s    = (const float*)d_in[19];
    const float* fb2s    = (const float*)d_in[20];
    const float* fW2v    = (const float*)d_in[21];
    const int*   atom    = (const int*)d_in[22];
    const int*   esrc    = (const int*)d_in[23];
    const int*   edst    = (const int*)d_in[24];
    float* out = (float*)d_out;

    const int SM_DEG = (3584 + 4096 + 8192 + 64 + 64 + 128 + 64) * 4;   // 64,768B
    const int SM_ATT = (20480 + 320 + 64) * 4;                           // 83,456B
    const int SM_ND  = (4096 + 4096 + 64*128) * 4;
    const int SM_PA  = (4096 + 4096 + 8192 + 128 + 64*128) * 4;
    const int SM_PB  = (4096*3 + 64 + 64*128) * 4;
    cudaFuncSetAttribute(k_edge_deg,   cudaFuncAttributeMaxDynamicSharedMemorySize, SM_DEG);
    cudaFuncSetAttribute(k_edge_attn,  cudaFuncAttributeMaxDynamicSharedMemorySize, SM_ATT);
    cudaFuncSetAttribute(k_node_deg,   cudaFuncAttributeMaxDynamicSharedMemorySize, SM_ND);
    cudaFuncSetAttribute(k_node_postA, cudaFuncAttributeMaxDynamicSharedMemorySize, SM_PA);
    cudaFuncSetAttribute(k_node_postB, cudaFuncAttributeMaxDynamicSharedMemorySize, SM_PB);

    int eb2 = (NE + 511) / 512;
    int nb  = (NN + 127) / 128;
    k_zero<<<592, 256>>>();
    k_edge_deg<<<eb2, 256, SM_DEG>>>(pos, exp_w, rW1, rb1, rW2, rb2, rWdeg, rbdeg, esrc, edst);
    k_node_deg<<<nb, 128, SM_ND>>>(embed_W, dp0, dp1, atom);
    k_edge_attn<<<eb2, 256, SM_ATT>>>(rWattn, rbattn, adot, esrc, edst);
    k_edge_agg<<<eb2, 256>>>(edst);
    k_node_postA<<<nb, 128, SM_PA>>>(op0, op1, fW1s, fb1s);
    k_node_postB<<<nb, 128, SM_PB>>>(fW2s, fb2s, fW1v, fW2v, out);
}

// round 11
// speedup vs baseline: 1.0206x; 1.0206x over previous
#include <cuda_runtime.h>
#include <cstdint>

#define NN 50000
#define NE 800000
typedef unsigned long long ull;

// ---------------- scratch -----------------------------------------------
__device__ __align__(128) float    g_Y1[3 * NE];
__device__ __align__(128) float    g_h1[(size_t)64 * NE];
__device__ __align__(128) float    g_hmid[(size_t)64 * NE];
__device__ __align__(128) float    g_acc0[(size_t)NN * 64];
__device__ __align__(128) float    g_acc1[(size_t)NN * 192];
__device__ __align__(128) float    g_f0[(size_t)NN * 64];
__device__ __align__(128) float    g_f1[(size_t)NN * 192];
__device__ __align__(128) float    g_msg0[(size_t)64 * NE];
__device__ __align__(128) float    g_msg1[(size_t)192 * NE];
__device__ __align__(128) float    g_a[(size_t)8 * NE];
__device__ __align__(128) unsigned g_amax[(size_t)NN * 8];
__device__ __align__(128) float    g_z[(size_t)NN * 8];
__device__ __align__(128) float    g_agg0[(size_t)NN * 64];
__device__ __align__(128) float    g_agg1[(size_t)NN * 192];
__device__ __align__(128) float    g_mid[(size_t)NN * 64];
__device__ __align__(128) float    g_gateT[(size_t)64 * NN];

// ---------------- helpers ------------------------------------------------
__device__ __forceinline__ void red4(float* p, float a, float b, float c, float d) {
    asm volatile("red.global.add.v4.f32 [%0], {%1,%2,%3,%4};"
                 :: "l"(p), "f"(a), "f"(b), "f"(c), "f"(d) : "memory");
}
__device__ __forceinline__ unsigned fkey(float x) {
    unsigned u = __float_as_uint(x);
    return (u & 0x80000000u) ? ~u : (u | 0x80000000u);
}
__device__ __forceinline__ float fdec(unsigned k) {
    return (k & 0x80000000u) ? __uint_as_float(k & 0x7FFFFFFFu) : __uint_as_float(~k);
}
__device__ __forceinline__ float sigf(float x) { return __fdividef(1.f, 1.f + __expf(-x)); }
__device__ __forceinline__ float siluf(float x) { return x * sigf(x); }

__device__ __forceinline__ ull pack2(float a) {
    ull r; unsigned u = __float_as_uint(a);
    asm("mov.b64 %0,{%1,%1};" : "=l"(r) : "r"(u));
    return r;
}
#define FMA2(acc, a, b) asm("fma.rn.f32x2 %0,%1,%2,%0;" : "+l"(acc) : "l"(a), "l"(b))
__device__ __forceinline__ float2 unpack2(ull v) {
    unsigned lo, hi;
    asm("mov.b64 {%0,%1},%2;" : "=r"(lo), "=r"(hi) : "l"(v));
    return make_float2(__uint_as_float(lo), __uint_as_float(hi));
}

// 64-output GEMV for ONE node. x in smem column sx[c*BT+tid].
template<int NCH, int LDW, int BT>
__device__ __forceinline__ void gemv_s(const float* __restrict__ sW,
                                       const float* __restrict__ sx, int tid,
                                       ull* __restrict__ y) {
#pragma unroll 1
    for (int c0 = 0; c0 < NCH; c0++) {
        const float* xp = sx + (c0 * 8) * BT + tid;
        const float* wb = sW + (c0 * 8) * LDW;
        float xc[8];
#pragma unroll
        for (int i = 0; i < 8; i++) xc[i] = xp[i * BT];
#pragma unroll
        for (int i = 0; i < 8; i++) {
            ull xx = pack2(xc[i]);
            const ulonglong2* wp = (const ulonglong2*)(wb + i * LDW);
#pragma unroll
            for (int d = 0; d < 16; d++) {
                ulonglong2 w = wp[d];
                FMA2(y[2*d],   xx, w.x);
                FMA2(y[2*d+1], xx, w.y);
            }
        }
    }
}

// 32-output GEMV for TWO ADJACENT edges; x streamed from gmem (L2-hot) via
// LDG.64, double-buffered. sW row-major LDW, 32 consecutive output columns.
template<int LDW>
__device__ __forceinline__ void gemv2g(const float* __restrict__ sW,
                                       const float* __restrict__ gx,  // + e0
                                       ull* __restrict__ y0, ull* __restrict__ y1) {
    float2 xc[8], xn[8];
#pragma unroll
    for (int i = 0; i < 8; i++) xc[i] = *(const float2*)(gx + (size_t)i * NE);
#pragma unroll 1
    for (int c0 = 0; c0 < 8; c0++) {
        if (c0 < 7) {
#pragma unroll
            for (int i = 0; i < 8; i++)
                xn[i] = *(const float2*)(gx + (size_t)((c0+1)*8 + i) * NE);
        }
#pragma unroll
        for (int j = 0; j < 8; j++) {
            ull x0 = pack2(xc[j].x), x1 = pack2(xc[j].y);
            const ulonglong2* wp = (const ulonglong2*)(sW + (c0*8 + j) * LDW);
#pragma unroll
            for (int d = 0; d < 8; d++) {
                ulonglong2 w = wp[d];
                FMA2(y0[2*d],   x0, w.x); FMA2(y0[2*d+1], x0, w.y);
                FMA2(y1[2*d],   x1, w.x); FMA2(y1[2*d+1], x1, w.y);
            }
        }
#pragma unroll
        for (int i = 0; i < 8; i++) xc[i] = xn[i];
    }
}
__device__ __forceinline__ void initp16(ull* y, const float* b) {
#pragma unroll
    for (int i = 0; i < 16; i++) y[i] = *(const ull*)(b + 2*i);
}
__device__ __forceinline__ void zerop(ull* y) {
#pragma unroll
    for (int i = 0; i < 32; i++) y[i] = 0ull;
}

// ---------------- K0: zero ----------------------------------------------
__global__ void k_zero() {
    int t = blockIdx.x * blockDim.x + threadIdx.x, s = gridDim.x * blockDim.x;
    for (int i = t; i < NN * 64;  i += s) { g_acc0[i] = 0.f; g_agg0[i] = 0.f; }
    for (int i = t; i < NN * 192; i += s) { g_acc1[i] = 0.f; g_agg1[i] = 0.f; }
    for (int i = t; i < NN * 8;   i += s) { g_z[i] = 0.f; g_amax[i] = 0u; }
}

// ---------------- K1: edge RBF + MLP + degree scatter ---------------------
__global__ void __launch_bounds__(256, 2) k_edge_deg(
    const float* __restrict__ pos, const float* __restrict__ exp_w,
    const float* __restrict__ W1, const float* __restrict__ b1,
    const float* __restrict__ W2, const float* __restrict__ b2,
    const float* __restrict__ Wdeg, const float* __restrict__ bdeg,
    const int* __restrict__ esrc, const int* __restrict__ edst)
{
    extern __shared__ float sm[];
    float* sW1 = sm;            // 3584 (rows 50..55 zero)
    float* sW2 = sW1 + 3584;    // 4096
    float* sWd = sW2 + 4096;    // 8192
    float* sb1 = sWd + 8192;    // 64
    float* sb2 = sb1 + 64;      // 64
    float* sbd = sb2 + 64;      // 128
    float* sew = sbd + 128;     // 64
    for (int i = threadIdx.x; i < 3584; i += 256) sW1[i] = (i < 3200) ? W1[i] : 0.f;
    for (int i = threadIdx.x; i < 4096; i += 256) sW2[i] = W2[i];
    for (int i = threadIdx.x; i < 8192; i += 256) sWd[i] = Wdeg[i];
    if (threadIdx.x < 64) { sb1[threadIdx.x] = b1[threadIdx.x];
                            sb2[threadIdx.x] = b2[threadIdx.x];
                            sew[threadIdx.x] = exp_w[threadIdx.x]; }
    if (threadIdx.x < 128) sbd[threadIdx.x] = bdeg[threadIdx.x];
    __syncthreads();

    int tid = threadIdx.x;
    int e0 = blockIdx.x * 512 + 2 * tid;
    if (e0 >= NE) return;
    int2 ss = *(const int2*)&esrc[e0];
    int2 dd = *(const int2*)&edst[e0];
    int s0 = ss.x, s1 = ss.y, d0 = dd.x, d1 = dd.y;

    float y00, y01, y02, ed0, cut0, y10, y11, y12, ed1, cut1;
    {
        float dx = pos[3*d0]-pos[3*s0], dy = pos[3*d0+1]-pos[3*s0+1], dz = pos[3*d0+2]-pos[3*s0+2];
        float dist = sqrtf(dx*dx + dy*dy + dz*dz + 1e-9f);
        float ri = __fdividef(1.f, dist);
        y00 = dx*ri; y01 = dy*ri; y02 = dz*ri;
        cut0 = (dist < 5.f) ? 0.5f * (__cosf(0.6283185307179586f * dist) + 1.f) : 0.f;
        ed0 = __expf(-dist);
    }
    {
        float dx = pos[3*d1]-pos[3*s1], dy = pos[3*d1+1]-pos[3*s1+1], dz = pos[3*d1+2]-pos[3*s1+2];
        float dist = sqrtf(dx*dx + dy*dy + dz*dz + 1e-9f);
        float ri = __fdividef(1.f, dist);
        y10 = dx*ri; y11 = dy*ri; y12 = dz*ri;
        cut1 = (dist < 5.f) ? 0.5f * (__cosf(0.6283185307179586f * dist) + 1.f) : 0.f;
        ed1 = __expf(-dist);
    }
    *(float2*)&g_Y1[e0]      = make_float2(y00, y10);
    *(float2*)&g_Y1[NE+e0]   = make_float2(y01, y11);
    *(float2*)&g_Y1[2*NE+e0] = make_float2(y02, y12);

    const float startc = 0.006737946999085467f;
    const float stepc  = (1.f - startc) / 49.f;
    const float bbq    = 0.04f * (1.f - startc);
    const float beta   = 1.f / (bbq * bbq);

    ull a0[16], a1[16];
    // ---- stage 1: rbf @ W1 -> h1 (gmem) ----
#pragma unroll 1
    for (int ch = 0; ch < 2; ch++) {
        initp16(a0, sb1 + ch*32); initp16(a1, sb1 + ch*32);
        const float* wbase = sW1 + ch*32;
#pragma unroll 1
        for (int c0 = 0; c0 < 7; c0++) {
            float xa[8], xb[8];
#pragma unroll
            for (int j = 0; j < 8; j++) {
                int i = c0*8 + j;
                float mi = startc + stepc * (float)i;
                float t0v = ed0 - mi, t1v = ed1 - mi;
                xa[j] = cut0 * __expf(-beta * t0v * t0v);
                xb[j] = cut1 * __expf(-beta * t1v * t1v);
            }
#pragma unroll
            for (int j = 0; j < 8; j++) {
                ull x0 = pack2(xa[j]), x1 = pack2(xb[j]);
                const ulonglong2* wp = (const ulonglong2*)(wbase + (c0*8 + j)*64);
#pragma unroll
                for (int d = 0; d < 8; d++) {
                    ulonglong2 w = wp[d];
                    FMA2(a0[2*d], x0, w.x); FMA2(a0[2*d+1], x0, w.y);
                    FMA2(a1[2*d], x1, w.x); FMA2(a1[2*d+1], x1, w.y);
                }
            }
        }
#pragma unroll
        for (int i = 0; i < 16; i++) {
            float2 u = unpack2(a0[i]), v = unpack2(a1[i]);
            int r = ch*32 + 2*i;
            *(float2*)&g_h1[(size_t)r*NE + e0]     = make_float2(siluf(u.x), siluf(v.x));
            *(float2*)&g_h1[(size_t)(r+1)*NE + e0] = make_float2(siluf(u.y), siluf(v.y));
        }
    }
    // ---- stage 2: h1 @ W2 -> h2 (g_hmid) ----
#pragma unroll 1
    for (int ch = 0; ch < 2; ch++) {
        initp16(a0, sb2 + ch*32); initp16(a1, sb2 + ch*32);
        gemv2g<64>(sW2 + ch*32, g_h1 + e0, a0, a1);
#pragma unroll
        for (int i = 0; i < 16; i++) {
            float2 u = unpack2(a0[i]), v = unpack2(a1[i]);
            int r = ch*32 + 2*i;
            *(float2*)&g_hmid[(size_t)r*NE + e0]     = make_float2(siluf(u.x), siluf(v.x));
            *(float2*)&g_hmid[(size_t)(r+1)*NE + e0] = make_float2(siluf(u.y), siluf(v.y));
        }
    }
    // ---- stage 3: wd0 scatter ----
#pragma unroll 1
    for (int ch = 0; ch < 2; ch++) {
        initp16(a0, sbd + ch*32); initp16(a1, sbd + ch*32);
        gemv2g<128>(sWd + ch*32, g_hmid + e0, a0, a1);
#pragma unroll
        for (int q = 0; q < 8; q++) {
            int c = ch*32 + 4*q;
            float2 p0 = unpack2(a0[2*q]), p1 = unpack2(a0[2*q+1]);
            red4(&g_acc0[d0*64 + c], p0.x*sew[c], p0.y*sew[c+1], p1.x*sew[c+2], p1.y*sew[c+3]);
            float2 q0 = unpack2(a1[2*q]), q1 = unpack2(a1[2*q+1]);
            red4(&g_acc0[d1*64 + c], q0.x*sew[c], q0.y*sew[c+1], q1.x*sew[c+2], q1.y*sew[c+3]);
        }
    }
    // ---- stage 4: wd1 scatter (outer with Y1) ----
#pragma unroll 1
    for (int ch = 0; ch < 2; ch++) {
        initp16(a0, sbd + 64 + ch*32); initp16(a1, sbd + 64 + ch*32);
        gemv2g<128>(sWd + 64 + ch*32, g_hmid + e0, a0, a1);
#pragma unroll
        for (int q = 0; q < 8; q++) {
            int c = ch*32 + 4*q;
            float2 p0 = unpack2(a0[2*q]), p1 = unpack2(a0[2*q+1]);
            float w0 = p0.x*sew[c], w1 = p0.y*sew[c+1], w2 = p1.x*sew[c+2], w3 = p1.y*sew[c+3];
#pragma unroll
            for (int i = 0; i < 3; i++) {
                float yi = (i == 0) ? y00 : ((i == 1) ? y01 : y02);
                red4(&g_acc1[(size_t)d0*192 + i*64 + c], w0*yi, w1*yi, w2*yi, w3*yi);
            }
            float2 q0 = unpack2(a1[2*q]), q1 = unpack2(a1[2*q+1]);
            float u0 = q0.x*sew[c], u1 = q0.y*sew[c+1], u2 = q1.x*sew[c+2], u3 = q1.y*sew[c+3];
#pragma unroll
            for (int i = 0; i < 3; i++) {
                float yi = (i == 0) ? y10 : ((i == 1) ? y11 : y12);
                red4(&g_acc1[(size_t)d1*192 + i*64 + c], u0*yi, u1*yi, u2*yi, u3*yi);
            }
        }
    }
}

// ---------------- K2: node embed + deg proj ------------------------------
__global__ void __launch_bounds__(128) k_node_deg(
    const float* __restrict__ embed_W, const float* __restrict__ P0,
    const float* __restrict__ P1, const int* __restrict__ atom)
{
    extern __shared__ float sm[];
    float* sP0 = sm; float* sP1 = sP0 + 4096; float* sx = sP1 + 4096;
    for (int i = threadIdx.x; i < 4096; i += 128) { sP0[i] = P0[i]; sP1[i] = P1[i]; }
    __syncthreads();
    int tid = threadIdx.x;
    int n = blockIdx.x * 128 + tid;
    if (n >= NN) return;
    int at = atom[n];
    ull acc[32];
#pragma unroll
    for (int g = 0; g < 16; g++) { float4 v = ((const float4*)(g_acc0 + n*64))[g];
        sx[(4*g)*128+tid]=v.x; sx[(4*g+1)*128+tid]=v.y; sx[(4*g+2)*128+tid]=v.z; sx[(4*g+3)*128+tid]=v.w; }
    zerop(acc);
    gemv_s<8, 64, 128>(sP0, sx, tid, acc);
#pragma unroll
    for (int i = 0; i < 32; i++) { float2 v = unpack2(acc[i]);
        g_f0[n*64 + 2*i]   = embed_W[at*64 + 2*i]   + 0.25f * v.x;
        g_f0[n*64 + 2*i+1] = embed_W[at*64 + 2*i+1] + 0.25f * v.y; }
#pragma unroll 1
    for (int i = 0; i < 3; i++) {
#pragma unroll
        for (int g = 0; g < 16; g++) { float4 v = ((const float4*)(g_acc1 + (size_t)n*192 + i*64))[g];
            sx[(4*g)*128+tid]=v.x; sx[(4*g+1)*128+tid]=v.y; sx[(4*g+2)*128+tid]=v.z; sx[(4*g+3)*128+tid]=v.w; }
        zerop(acc);
        gemv_s<8, 64, 128>(sP1, sx, tid, acc);
#pragma unroll
        for (int j = 0; j < 32; j++) { float2 v = unpack2(acc[j]);
            g_f1[(size_t)n*192 + i*64 + 2*j]   = 0.25f * v.x;
            g_f1[(size_t)n*192 + i*64 + 2*j+1] = 0.25f * v.y; }
    }
}

// ---------------- K3: edge attention (pair of edges, pair of g-columns) ---
__global__ void __launch_bounds__(256, 2) k_edge_attn(
    const float* __restrict__ Wattn, const float* __restrict__ battn,
    const float* __restrict__ alpha_dot,
    const int* __restrict__ esrc, const int* __restrict__ edst)
{
    extern __shared__ float sm[];
    float* sW  = sm;                // 20480
    float* sb  = sW + 20480;        // 320
    float* sad = sb + 320;          // 64
    for (int i = threadIdx.x; i < 20480; i += 256) sW[i] = Wattn[i];
    for (int i = threadIdx.x; i < 320; i += 256) sb[i] = battn[i];
    if (threadIdx.x < 64) sad[threadIdx.x] = alpha_dot[threadIdx.x];
    __syncthreads();

    int tid = threadIdx.x;
    int e0 = blockIdx.x * 512 + 2 * tid;
    if (e0 >= NE) return;
    int2 ss = *(const int2*)&esrc[e0];
    int2 dd = *(const int2*)&edst[e0];
    int s0 = ss.x, s1 = ss.y, d0 = dd.x, d1 = dd.y;
    float2 yv0 = *(const float2*)&g_Y1[e0];
    float2 yv1 = *(const float2*)&g_Y1[NE+e0];
    float2 yv2 = *(const float2*)&g_Y1[2*NE+e0];
    float y00 = yv0.x, y01 = yv1.x, y02 = yv2.x;
    float y10 = yv0.y, y11 = yv1.y, y12 = yv2.y;

    const float4* f0p0 = (const float4*)(g_f0 + (size_t)s0*64);
    const float4* f1p0 = (const float4*)(g_f1 + (size_t)s0*192);
    const float4* f0p1 = (const float4*)(g_f0 + (size_t)s1*64);
    const float4* f1p1 = (const float4*)(g_f1 + (size_t)s1*192);
    const float is3 = 0.5773502691896258f, is2 = 0.7071067811865476f;

#pragma unroll 1
    for (int gp = 0; gp < 8; gp++) {
        // acc[t][q][h]: t = g-column within pair (g = 2*gp + t)
        ull acc0[2][5][2], acc1[2][5][2];
#pragma unroll
        for (int t = 0; t < 2; t++)
#pragma unroll
            for (int q = 0; q < 5; q++) {
                int g = 2*gp + t;
                ull b0 = *(const ull*)(sb + q*64 + 4*g);
                ull b1 = *(const ull*)(sb + q*64 + 4*g + 2);
                acc0[t][q][0] = b0; acc0[t][q][1] = b1;
                acc1[t][q][0] = b0; acc1[t][q][1] = b1;
            }
        // k-sweep once per g-PAIR: hmid stream read 8x total instead of 16x
#pragma unroll 1
        for (int k0 = 0; k0 < 8; k0++) {
            float2 xc[8];
#pragma unroll
            for (int i = 0; i < 8; i++)
                xc[i] = *(const float2*)(g_hmid + (size_t)(k0*8 + i)*NE + e0);
#pragma unroll
            for (int i = 0; i < 8; i++) {
                ull x0 = pack2(xc[i].x), x1 = pack2(xc[i].y);
                const float* wb = sW + (k0*8 + i)*320 + 8*gp;
#pragma unroll
                for (int q = 0; q < 5; q++) {
                    ulonglong2 wA = *(const ulonglong2*)(wb + q*64);
                    ulonglong2 wB = *(const ulonglong2*)(wb + q*64 + 4);
                    FMA2(acc0[0][q][0], x0, wA.x); FMA2(acc0[0][q][1], x0, wA.y);
                    FMA2(acc1[0][q][0], x1, wA.x); FMA2(acc1[0][q][1], x1, wA.y);
                    FMA2(acc0[1][q][0], x0, wB.x); FMA2(acc0[1][q][1], x0, wB.y);
                    FMA2(acc1[1][q][0], x1, wB.x); FMA2(acc1[1][q][1], x1, wB.y);
                }
            }
        }
        // ---- epilogue: both g's of the pair, both edges ----
        float hsum0 = 0.f, hsum1 = 0.f;
#pragma unroll
        for (int t = 0; t < 2; t++) {
            int g = 2*gp + t;
            float wq0[5][4], wq1[5][4];
#pragma unroll
            for (int q = 0; q < 5; q++) {
                float2 a = unpack2(acc0[t][q][0]), b = unpack2(acc0[t][q][1]);
                wq0[q][0] = a.x; wq0[q][1] = a.y; wq0[q][2] = b.x; wq0[q][3] = b.y;
                float2 c = unpack2(acc1[t][q][0]), d = unpack2(acc1[t][q][1]);
                wq1[q][0] = c.x; wq1[q][1] = c.y; wq1[q][2] = d.x; wq1[q][3] = d.y;
            }
            float4 P00 = f0p0[g], Pa0 = f1p0[g], Pb0 = f1p0[16+g], Pc0 = f1p0[32+g];
            float4 P01 = f0p1[g], Pa1 = f1p1[g], Pb1 = f1p1[16+g], Pc1 = f1p1[32+g];
            float s0v0[4] = {P00.x,P00.y,P00.z,P00.w};
            float a0v0[4] = {Pa0.x,Pa0.y,Pa0.z,Pa0.w};
            float a1v0[4] = {Pb0.x,Pb0.y,Pb0.z,Pb0.w};
            float a2v0[4] = {Pc0.x,Pc0.y,Pc0.z,Pc0.w};
            float s0v1[4] = {P01.x,P01.y,P01.z,P01.w};
            float a0v1[4] = {Pa1.x,Pa1.y,Pa1.z,Pa1.w};
            float a1v1[4] = {Pb1.x,Pb1.y,Pb1.z,Pb1.w};
            float a2v1[4] = {Pc1.x,Pc1.y,Pc1.z,Pc1.w};
#pragma unroll
            for (int u = 0; u < 4; u++) {
                int c = 4*g + u;
                float m00, m10a, m11a, m12a;
                {
                    float w0 = wq0[0][u], w1 = wq0[1][u], w2 = wq0[2][u], w3 = wq0[3][u], w4 = wq0[4][u];
                    float s0c = s0v0[u], a0 = a0v0[u], a1 = a1v0[u], a2 = a2v0[u];
                    float dot = a0*y00 + a1*y01 + a2*y02;
                    m00 = w0*s0c + w3*dot*is3;
                    float cx = a1*y02 - a2*y01, cy = a2*y00 - a0*y02, cz = a0*y01 - a1*y00;
                    m10a = w1*s0c*y00 + w2*a0 + w4*cx*is2;
                    m11a = w1*s0c*y01 + w2*a1 + w4*cy*is2;
                    m12a = w1*s0c*y02 + w2*a2 + w4*cz*is2;
                    hsum0 += (0.2f*m00 + 0.8f*m00*sigf(m00)) * sad[c];
                }
                float m01, m10b, m11b, m12b;
                {
                    float w0 = wq1[0][u], w1 = wq1[1][u], w2 = wq1[2][u], w3 = wq1[3][u], w4 = wq1[4][u];
                    float s0c = s0v1[u], a0 = a0v1[u], a1 = a1v1[u], a2 = a2v1[u];
                    float dot = a0*y10 + a1*y11 + a2*y12;
                    m01 = w0*s0c + w3*dot*is3;
                    float cx = a1*y12 - a2*y11, cy = a2*y10 - a0*y12, cz = a0*y11 - a1*y10;
                    m10b = w1*s0c*y10 + w2*a0 + w4*cx*is2;
                    m11b = w1*s0c*y11 + w2*a1 + w4*cy*is2;
                    m12b = w1*s0c*y12 + w2*a2 + w4*cz*is2;
                    hsum1 += (0.2f*m01 + 0.8f*m01*sigf(m01)) * sad[c];
                }
                *(float2*)&g_msg0[(size_t)c*NE + e0]          = make_float2(m00, m01);
                *(float2*)&g_msg1[(size_t)(0*64+c)*NE + e0]   = make_float2(m10a, m10b);
                *(float2*)&g_msg1[(size_t)(1*64+c)*NE + e0]   = make_float2(m11a, m11b);
                *(float2*)&g_msg1[(size_t)(2*64+c)*NE + e0]   = make_float2(m12a, m12b);
            }
        }
        // whole pair belongs to head gp
        *(float2*)&g_a[(size_t)gp*NE + e0] = make_float2(hsum0, hsum1);
        atomicMax(&g_amax[d0*8 + gp], fkey(hsum0));
        atomicMax(&g_amax[d1*8 + gp], fkey(hsum1));
    }
}

// ---------------- K4: ea + z scatter + aggregation (fused, 2 edges) ------
__global__ void __launch_bounds__(256) k_edge_agg(const int* __restrict__ edst) {
    int tid = threadIdx.x;
    int e0 = blockIdx.x * 512 + 2 * tid;
    if (e0 >= NE) return;
    int2 dd = *(const int2*)&edst[e0];
    int d0 = dd.x, d1 = dd.y;
    float2 ea[8];
#pragma unroll
    for (int h = 0; h < 8; h++) {
        float2 a = *(const float2*)&g_a[(size_t)h*NE + e0];
        ea[h].x = __expf(a.x - fdec(g_amax[d0*8 + h]));
        ea[h].y = __expf(a.y - fdec(g_amax[d1*8 + h]));
    }
    red4(&g_z[d0*8],     ea[0].x, ea[1].x, ea[2].x, ea[3].x);
    red4(&g_z[d0*8 + 4], ea[4].x, ea[5].x, ea[6].x, ea[7].x);
    red4(&g_z[d1*8],     ea[0].y, ea[1].y, ea[2].y, ea[3].y);
    red4(&g_z[d1*8 + 4], ea[4].y, ea[5].y, ea[6].y, ea[7].y);
#pragma unroll
    for (int g = 0; g < 16; g++) {
        float2 w = ea[g >> 1];
        float2 m0 = *(const float2*)&g_msg0[(size_t)(4*g)*NE + e0];
        float2 m1 = *(const float2*)&g_msg0[(size_t)(4*g+1)*NE + e0];
        float2 m2 = *(const float2*)&g_msg0[(size_t)(4*g+2)*NE + e0];
        float2 m3 = *(const float2*)&g_msg0[(size_t)(4*g+3)*NE + e0];
        red4(&g_agg0[d0*64 + 4*g], m0.x*w.x, m1.x*w.x, m2.x*w.x, m3.x*w.x);
        red4(&g_agg0[d1*64 + 4*g], m0.y*w.y, m1.y*w.y, m2.y*w.y, m3.y*w.y);
#pragma unroll
        for (int i = 0; i < 3; i++) {
            float2 u0 = *(const float2*)&g_msg1[(size_t)(i*64 + 4*g)*NE + e0];
            float2 u1 = *(const float2*)&g_msg1[(size_t)(i*64 + 4*g+1)*NE + e0];
            float2 u2 = *(const float2*)&g_msg1[(size_t)(i*64 + 4*g+2)*NE + e0];
            float2 u3 = *(const float2*)&g_msg1[(size_t)(i*64 + 4*g+3)*NE + e0];
            red4(&g_agg1[(size_t)d0*192 + i*64 + 4*g], u0.x*w.x, u1.x*w.x, u2.x*w.x, u3.x*w.x);
            red4(&g_agg1[(size_t)d1*192 + i*64 + 4*g], u0.y*w.y, u1.y*w.y, u2.y*w.y, u3.y*w.y);
        }
    }
}

// ---------------- K6: node out_proj + FFN part A -------------------------
__global__ void __launch_bounds__(128) k_node_postA(
    const float* __restrict__ P0, const float* __restrict__ P1,
    const float* __restrict__ W1s, const float* __restrict__ b1s)
{
    extern __shared__ float sm[];
    float* sP0 = sm; float* sP1 = sP0 + 4096; float* sWs = sP1 + 4096;
    float* sbs = sWs + 8192; float* sx = sbs + 128;
    for (int i = threadIdx.x; i < 4096; i += 128) { sP0[i] = P0[i]; sP1[i] = P1[i]; }
    for (int i = threadIdx.x; i < 8192; i += 128) sWs[i] = W1s[i];
    if (threadIdx.x < 128) sbs[threadIdx.x] = b1s[threadIdx.x];
    __syncthreads();
    int tid = threadIdx.x;
    int n = blockIdx.x * 128 + tid;
    if (n >= NN) return;
    float rz[8];
#pragma unroll
    for (int h = 0; h < 8; h++) {
        float z = g_z[n*8 + h];
        rz[h] = (z > 0.f) ? __fdividef(1.f, z) : 0.f;
    }
    ull acc[32];
#pragma unroll
    for (int g = 0; g < 16; g++) { float4 v = ((const float4*)(g_agg0 + n*64))[g];
        float r = rz[g >> 1];
        sx[(4*g)*128+tid]=v.x*r; sx[(4*g+1)*128+tid]=v.y*r;
        sx[(4*g+2)*128+tid]=v.z*r; sx[(4*g+3)*128+tid]=v.w*r; }
    zerop(acc);
    gemv_s<8, 64, 128>(sP0, sx, tid, acc);
    float x[64];
#pragma unroll
    for (int i = 0; i < 32; i++) { float2 v = unpack2(acc[i]);
        float a = g_f0[n*64 + 2*i] + v.x, b = g_f0[n*64 + 2*i+1] + v.y;
        x[2*i] = a; x[2*i+1] = b;
        g_f0[n*64 + 2*i] = a; g_f0[n*64 + 2*i+1] = b;
        sx[(2*i)*128+tid] = a; sx[(2*i+1)*128+tid] = b; }
    zerop(acc);
    gemv_s<8, 128, 128>(sWs, sx, tid, acc);
#pragma unroll
    for (int i = 0; i < 32; i++) { float2 v = unpack2(acc[i]);
        g_mid[n*64 + 2*i]   = siluf(v.x + sbs[2*i]);
        g_mid[n*64 + 2*i+1] = siluf(v.y + sbs[2*i+1]); }
    zerop(acc);
    gemv_s<8, 128, 128>(sWs + 64, sx, tid, acc);
#pragma unroll
    for (int i = 0; i < 32; i++) { float2 v = unpack2(acc[i]);
        g_gateT[(size_t)(2*i)*NN + n]   = sigf(v.x + sbs[64 + 2*i]);
        g_gateT[(size_t)(2*i+1)*NN + n] = sigf(v.y + sbs[64 + 2*i+1]); }
#pragma unroll 1
    for (int i = 0; i < 3; i++) {
#pragma unroll
        for (int g = 0; g < 16; g++) { float4 v = ((const float4*)(g_agg1 + (size_t)n*192 + i*64))[g];
            float r = rz[g >> 1];
            sx[(4*g)*128+tid]=v.x*r; sx[(4*g+1)*128+tid]=v.y*r;
            sx[(4*g+2)*128+tid]=v.z*r; sx[(4*g+3)*128+tid]=v.w*r; }
        zerop(acc);
        gemv_s<8, 64, 128>(sP1, sx, tid, acc);
#pragma unroll
        for (int j = 0; j < 32; j++) { float2 v = unpack2(acc[j]);
            g_f1[(size_t)n*192 + i*64 + 2*j]   += v.x;
            g_f1[(size_t)n*192 + i*64 + 2*j+1] += v.y; }
    }
}

// ---------------- K7: node FFN part B + output ---------------------------
__global__ void __launch_bounds__(128) k_node_postB(
    const float* __restrict__ W2s, const float* __restrict__ b2s,
    const float* __restrict__ W1v, const float* __restrict__ W2v,
    float* __restrict__ out)
{
    extern __shared__ float sm[];
    float* sWs = sm; float* sWa = sWs + 4096; float* sWb = sWa + 4096;
    float* sb2 = sWb + 4096; float* sx = sb2 + 64;
    for (int i = threadIdx.x; i < 4096; i += 128) { sWs[i] = W2s[i]; sWa[i] = W1v[i]; sWb[i] = W2v[i]; }
    if (threadIdx.x < 64) sb2[threadIdx.x] = b2s[threadIdx.x];
    __syncthreads();
    int tid = threadIdx.x;
    int n = blockIdx.x * 128 + tid;
    if (n >= NN) return;
    ull acc[32];
#pragma unroll
    for (int g = 0; g < 16; g++) { float4 v = ((const float4*)(g_mid + n*64))[g];
        sx[(4*g)*128+tid]=v.x; sx[(4*g+1)*128+tid]=v.y;
        sx[(4*g+2)*128+tid]=v.z; sx[(4*g+3)*128+tid]=v.w; }
    zerop(acc);
    gemv_s<8, 64, 128>(sWs, sx, tid, acc);
#pragma unroll
    for (int i = 0; i < 32; i++) { float2 v = unpack2(acc[i]);
        out[(size_t)n*256 + 2*i]   = g_f0[n*64 + 2*i]   + v.x + sb2[2*i];
        out[(size_t)n*256 + 2*i+1] = g_f0[n*64 + 2*i+1] + v.y + sb2[2*i+1]; }

    float gate[64];
#pragma unroll
    for (int j = 0; j < 64; j++) gate[j] = g_gateT[(size_t)j*NN + n];
#pragma unroll 1
    for (int i = 0; i < 3; i++) {
        float x[64];
#pragma unroll
        for (int g = 0; g < 16; g++) { float4 v = ((const float4*)(g_f1 + (size_t)n*192 + i*64))[g];
            x[4*g]=v.x; x[4*g+1]=v.y; x[4*g+2]=v.z; x[4*g+3]=v.w;
            sx[(4*g)*128+tid]=v.x; sx[(4*g+1)*128+tid]=v.y;
            sx[(4*g+2)*128+tid]=v.z; sx[(4*g+3)*128+tid]=v.w; }
        zerop(acc);
        gemv_s<8, 64, 128>(sWa, sx, tid, acc);
#pragma unroll
        for (int j = 0; j < 32; j++) { float2 v = unpack2(acc[j]);
            sx[(2*j)*128+tid]   = v.x * gate[2*j];
            sx[(2*j+1)*128+tid] = v.y * gate[2*j+1]; }
        zerop(acc);
        gemv_s<8, 64, 128>(sWb, sx, tid, acc);
#pragma unroll
        for (int j = 0; j < 32; j++) { float2 v = unpack2(acc[j]);
            out[(size_t)n*256 + 64 + (2*j)*3 + i]   = x[2*j]   + v.x;
            out[(size_t)n*256 + 64 + (2*j+1)*3 + i] = x[2*j+1] + v.y; }
    }
}

// ---------------- launch -------------------------------------------------
extern "C" void kernel_launch(void* const* d_in, const int* in_sizes, int n_in,
                              void* d_out, int out_size) {
    const float* pos     = (const float*)d_in[0];
    const float* embed_W = (const float*)d_in[1];
    const float* exp_w   = (const float*)d_in[2];
    const float* rW1     = (const float*)d_in[3];
    const float* rb1     = (const float*)d_in[4];
    const float* rW2     = (const float*)d_in[5];
    const float* rb2     = (const float*)d_in[6];
    const float* rWdeg   = (const float*)d_in[7];
    const float* rbdeg   = (const float*)d_in[8];
    const float* rWattn  = (const float*)d_in[9];
    const float* rbattn  = (const float*)d_in[10];
    const float* dp0     = (const float*)d_in[11];
    const float* dp1     = (const float*)d_in[12];
    const float* adot    = (const float*)d_in[13];
    const float* op0     = (const float*)d_in[14];
    const float* op1     = (const float*)d_in[15];
    const float* fW1s    = (const float*)d_in[16];
    const float* fb1s    = (const float*)d_in[17];
    const float* fW1v    = (const float*)d_in[18];
    const float* fW2s    = (const float*)d_in[19];
    const float* fb2s    = (const float*)d_in[20];
    const float* fW2v    = (const float*)d_in[21];
    const int*   atom    = (const int*)d_in[22];
    const int*   esrc    = (const int*)d_in[23];
    const int*   edst    = (const int*)d_in[24];
    float* out = (float*)d_out;

    const int SM_DEG = (3584 + 4096 + 8192 + 64 + 64 + 128 + 64) * 4;
    const int SM_ATT = (20480 + 320 + 64) * 4;
    const int SM_ND  = (4096 + 4096 + 64*128) * 4;
    const int SM_PA  = (4096 + 4096 + 8192 + 128 + 64*128) * 4;
    const int SM_PB  = (4096*3 + 64 + 64*128) * 4;
    cudaFuncSetAttribute(k_edge_deg,   cudaFuncAttributeMaxDynamicSharedMemorySize, SM_DEG);
    cudaFuncSetAttribute(k_edge_attn,  cudaFuncAttributeMaxDynamicSharedMemorySize, SM_ATT);
    cudaFuncSetAttribute(k_node_deg,   cudaFuncAttributeMaxDynamicSharedMemorySize, SM_ND);
    cudaFuncSetAttribute(k_node_postA, cudaFuncAttributeMaxDynamicSharedMemorySize, SM_PA);
    cudaFuncSetAttribute(k_node_postB, cudaFuncAttributeMaxDynamicSharedMemorySize, SM_PB);

    int eb2 = (NE + 511) / 512;
    int nb  = (NN + 127) / 128;
    k_zero<<<592, 256>>>();
    k_edge_deg<<<eb2, 256, SM_DEG>>>(pos, exp_w, rW1, rb1, rW2, rb2, rWdeg, rbdeg, esrc, edst);
    k_node_deg<<<nb, 128, SM_ND>>>(embed_W, dp0, dp1, atom);
    k_edge_attn<<<eb2, 256, SM_ATT>>>(rWattn, rbattn, adot, esrc, edst);
    k_edge_agg<<<eb2, 256>>>(edst);
    k_node_postA<<<nb, 128, SM_PA>>>(op0, op1, fW1s, fb1s);
    k_node_postB<<<nb, 128, SM_PB>>>(fW2s, fb2s, fW1v, fW2v, out);
}

// round 12
// speedup vs baseline: 1.0599x; 1.0385x over previous
#include <cuda_runtime.h>
#include <cstdint>

#define NN 50000
#define NE 800000
typedef unsigned long long ull;

// ---------------- scratch -----------------------------------------------
__device__ __align__(128) float    g_Y1[3 * NE];
__device__ __align__(128) float    g_h1[(size_t)64 * NE];
__device__ __align__(128) float    g_hmid[(size_t)64 * NE];
__device__ __align__(128) float    g_acc0[(size_t)NN * 64];
__device__ __align__(128) float    g_acc1[(size_t)NN * 192];
__device__ __align__(128) float    g_f0[(size_t)NN * 64];
__device__ __align__(128) float    g_f1[(size_t)NN * 192];
__device__ __align__(128) float    g_msg0[(size_t)64 * NE];
__device__ __align__(128) float    g_msg1[(size_t)192 * NE];
__device__ __align__(128) float    g_a[(size_t)8 * NE];
__device__ __align__(128) unsigned g_amax[(size_t)NN * 8];
__device__ __align__(128) float    g_z[(size_t)NN * 8];
__device__ __align__(128) float    g_agg0[(size_t)NN * 64];
__device__ __align__(128) float    g_agg1[(size_t)NN * 192];
__device__ __align__(128) float    g_mid[(size_t)NN * 64];
__device__ __align__(128) float    g_gateT[(size_t)64 * NN];

// ---------------- helpers ------------------------------------------------
__device__ __forceinline__ void red4(float* p, float a, float b, float c, float d) {
    asm volatile("red.global.add.v4.f32 [%0], {%1,%2,%3,%4};"
                 :: "l"(p), "f"(a), "f"(b), "f"(c), "f"(d) : "memory");
}
__device__ __forceinline__ unsigned fkey(float x) {
    unsigned u = __float_as_uint(x);
    return (u & 0x80000000u) ? ~u : (u | 0x80000000u);
}
__device__ __forceinline__ float fdec(unsigned k) {
    return (k & 0x80000000u) ? __uint_as_float(k & 0x7FFFFFFFu) : __uint_as_float(~k);
}
__device__ __forceinline__ float sigf(float x) { return __fdividef(1.f, 1.f + __expf(-x)); }
__device__ __forceinline__ float siluf(float x) { return x * sigf(x); }

__device__ __forceinline__ ull pack2(float a) {
    ull r; unsigned u = __float_as_uint(a);
    asm("mov.b64 %0,{%1,%1};" : "=l"(r) : "r"(u));
    return r;
}
#define FMA2(acc, a, b) asm("fma.rn.f32x2 %0,%1,%2,%0;" : "+l"(acc) : "l"(a), "l"(b))
__device__ __forceinline__ float2 unpack2(ull v) {
    unsigned lo, hi;
    asm("mov.b64 {%0,%1},%2;" : "=r"(lo), "=r"(hi) : "l"(v));
    return make_float2(__uint_as_float(lo), __uint_as_float(hi));
}

// 64-output GEMV for ONE node. x in smem column sx[c*BT+tid].
template<int NCH, int LDW, int BT>
__device__ __forceinline__ void gemv_s(const float* __restrict__ sW,
                                       const float* __restrict__ sx, int tid,
                                       ull* __restrict__ y) {
#pragma unroll 1
    for (int c0 = 0; c0 < NCH; c0++) {
        const float* xp = sx + (c0 * 8) * BT + tid;
        const float* wb = sW + (c0 * 8) * LDW;
        float xc[8];
#pragma unroll
        for (int i = 0; i < 8; i++) xc[i] = xp[i * BT];
#pragma unroll
        for (int i = 0; i < 8; i++) {
            ull xx = pack2(xc[i]);
            const ulonglong2* wp = (const ulonglong2*)(wb + i * LDW);
#pragma unroll
            for (int d = 0; d < 16; d++) {
                ulonglong2 w = wp[d];
                FMA2(y[2*d],   xx, w.x);
                FMA2(y[2*d+1], xx, w.y);
            }
        }
    }
}

// 32-output GEMV for TWO ADJACENT edges; x streamed from gmem (L2-hot) via
// LDG.64, double-buffered. sW row-major LDW, 32 consecutive output columns.
template<int LDW>
__device__ __forceinline__ void gemv2g(const float* __restrict__ sW,
                                       const float* __restrict__ gx,  // + e0
                                       ull* __restrict__ y0, ull* __restrict__ y1) {
    float2 xc[8], xn[8];
#pragma unroll
    for (int i = 0; i < 8; i++) xc[i] = *(const float2*)(gx + (size_t)i * NE);
#pragma unroll 1
    for (int c0 = 0; c0 < 8; c0++) {
        if (c0 < 7) {
#pragma unroll
            for (int i = 0; i < 8; i++)
                xn[i] = *(const float2*)(gx + (size_t)((c0+1)*8 + i) * NE);
        }
#pragma unroll
        for (int j = 0; j < 8; j++) {
            ull x0 = pack2(xc[j].x), x1 = pack2(xc[j].y);
            const ulonglong2* wp = (const ulonglong2*)(sW + (c0*8 + j) * LDW);
#pragma unroll
            for (int d = 0; d < 8; d++) {
                ulonglong2 w = wp[d];
                FMA2(y0[2*d],   x0, w.x); FMA2(y0[2*d+1], x0, w.y);
                FMA2(y1[2*d],   x1, w.x); FMA2(y1[2*d+1], x1, w.y);
            }
        }
#pragma unroll
        for (int i = 0; i < 8; i++) xc[i] = xn[i];
    }
}
__device__ __forceinline__ void initp16(ull* y, const float* b) {
#pragma unroll
    for (int i = 0; i < 16; i++) y[i] = *(const ull*)(b + 2*i);
}
__device__ __forceinline__ void zerop(ull* y) {
#pragma unroll
    for (int i = 0; i < 32; i++) y[i] = 0ull;
}

// ---------------- K0: zero ----------------------------------------------
__global__ void k_zero() {
    int t = blockIdx.x * blockDim.x + threadIdx.x, s = gridDim.x * blockDim.x;
    for (int i = t; i < NN * 64;  i += s) { g_acc0[i] = 0.f; g_agg0[i] = 0.f; }
    for (int i = t; i < NN * 192; i += s) { g_acc1[i] = 0.f; g_agg1[i] = 0.f; }
    for (int i = t; i < NN * 8;   i += s) { g_z[i] = 0.f; g_amax[i] = 0u; }
}

// ---------------- K1: edge RBF + MLP + degree scatter ---------------------
__global__ void __launch_bounds__(256, 2) k_edge_deg(
    const float* __restrict__ pos, const float* __restrict__ exp_w,
    const float* __restrict__ W1, const float* __restrict__ b1,
    const float* __restrict__ W2, const float* __restrict__ b2,
    const float* __restrict__ Wdeg, const float* __restrict__ bdeg,
    const int* __restrict__ esrc, const int* __restrict__ edst)
{
    extern __shared__ float sm[];
    float* sW1 = sm;            // 3584 (rows 50..55 zero)
    float* sW2 = sW1 + 3584;    // 4096
    float* sWd = sW2 + 4096;    // 8192
    float* sb1 = sWd + 8192;    // 64
    float* sb2 = sb1 + 64;      // 64
    float* sbd = sb2 + 64;      // 128
    float* sew = sbd + 128;     // 64
    for (int i = threadIdx.x; i < 3584; i += 256) sW1[i] = (i < 3200) ? W1[i] : 0.f;
    for (int i = threadIdx.x; i < 4096; i += 256) sW2[i] = W2[i];
    for (int i = threadIdx.x; i < 8192; i += 256) sWd[i] = Wdeg[i];
    if (threadIdx.x < 64) { sb1[threadIdx.x] = b1[threadIdx.x];
                            sb2[threadIdx.x] = b2[threadIdx.x];
                            sew[threadIdx.x] = exp_w[threadIdx.x]; }
    if (threadIdx.x < 128) sbd[threadIdx.x] = bdeg[threadIdx.x];
    __syncthreads();

    int tid = threadIdx.x;
    int e0 = blockIdx.x * 512 + 2 * tid;
    if (e0 >= NE) return;
    int2 ss = *(const int2*)&esrc[e0];
    int2 dd = *(const int2*)&edst[e0];
    int s0 = ss.x, s1 = ss.y, d0 = dd.x, d1 = dd.y;

    float y00, y01, y02, ed0, cut0, y10, y11, y12, ed1, cut1;
    {
        float dx = pos[3*d0]-pos[3*s0], dy = pos[3*d0+1]-pos[3*s0+1], dz = pos[3*d0+2]-pos[3*s0+2];
        float dist = sqrtf(dx*dx + dy*dy + dz*dz + 1e-9f);
        float ri = __fdividef(1.f, dist);
        y00 = dx*ri; y01 = dy*ri; y02 = dz*ri;
        cut0 = (dist < 5.f) ? 0.5f * (__cosf(0.6283185307179586f * dist) + 1.f) : 0.f;
        ed0 = __expf(-dist);
    }
    {
        float dx = pos[3*d1]-pos[3*s1], dy = pos[3*d1+1]-pos[3*s1+1], dz = pos[3*d1+2]-pos[3*s1+2];
        float dist = sqrtf(dx*dx + dy*dy + dz*dz + 1e-9f);
        float ri = __fdividef(1.f, dist);
        y10 = dx*ri; y11 = dy*ri; y12 = dz*ri;
        cut1 = (dist < 5.f) ? 0.5f * (__cosf(0.6283185307179586f * dist) + 1.f) : 0.f;
        ed1 = __expf(-dist);
    }
    *(float2*)&g_Y1[e0]      = make_float2(y00, y10);
    *(float2*)&g_Y1[NE+e0]   = make_float2(y01, y11);
    *(float2*)&g_Y1[2*NE+e0] = make_float2(y02, y12);

    const float startc = 0.006737946999085467f;
    const float stepc  = (1.f - startc) / 49.f;
    const float bbq    = 0.04f * (1.f - startc);
    const float beta   = 1.f / (bbq * bbq);

    ull a0[16], a1[16];
    // ---- stage 1: rbf @ W1 -> h1 (gmem) ----
#pragma unroll 1
    for (int ch = 0; ch < 2; ch++) {
        initp16(a0, sb1 + ch*32); initp16(a1, sb1 + ch*32);
        const float* wbase = sW1 + ch*32;
#pragma unroll 1
        for (int c0 = 0; c0 < 7; c0++) {
            float xa[8], xb[8];
#pragma unroll
            for (int j = 0; j < 8; j++) {
                int i = c0*8 + j;
                float mi = startc + stepc * (float)i;
                float t0v = ed0 - mi, t1v = ed1 - mi;
                xa[j] = cut0 * __expf(-beta * t0v * t0v);
                xb[j] = cut1 * __expf(-beta * t1v * t1v);
            }
#pragma unroll
            for (int j = 0; j < 8; j++) {
                ull x0 = pack2(xa[j]), x1 = pack2(xb[j]);
                const ulonglong2* wp = (const ulonglong2*)(wbase + (c0*8 + j)*64);
#pragma unroll
                for (int d = 0; d < 8; d++) {
                    ulonglong2 w = wp[d];
                    FMA2(a0[2*d], x0, w.x); FMA2(a0[2*d+1], x0, w.y);
                    FMA2(a1[2*d], x1, w.x); FMA2(a1[2*d+1], x1, w.y);
                }
            }
        }
#pragma unroll
        for (int i = 0; i < 16; i++) {
            float2 u = unpack2(a0[i]), v = unpack2(a1[i]);
            int r = ch*32 + 2*i;
            *(float2*)&g_h1[(size_t)r*NE + e0]     = make_float2(siluf(u.x), siluf(v.x));
            *(float2*)&g_h1[(size_t)(r+1)*NE + e0] = make_float2(siluf(u.y), siluf(v.y));
        }
    }
    // ---- stage 2: h1 @ W2 -> h2 (g_hmid) ----
#pragma unroll 1
    for (int ch = 0; ch < 2; ch++) {
        initp16(a0, sb2 + ch*32); initp16(a1, sb2 + ch*32);
        gemv2g<64>(sW2 + ch*32, g_h1 + e0, a0, a1);
#pragma unroll
        for (int i = 0; i < 16; i++) {
            float2 u = unpack2(a0[i]), v = unpack2(a1[i]);
            int r = ch*32 + 2*i;
            *(float2*)&g_hmid[(size_t)r*NE + e0]     = make_float2(siluf(u.x), siluf(v.x));
            *(float2*)&g_hmid[(size_t)(r+1)*NE + e0] = make_float2(siluf(u.y), siluf(v.y));
        }
    }
    // ---- stage 3: wd0 scatter ----
#pragma unroll 1
    for (int ch = 0; ch < 2; ch++) {
        initp16(a0, sbd + ch*32); initp16(a1, sbd + ch*32);
        gemv2g<128>(sWd + ch*32, g_hmid + e0, a0, a1);
#pragma unroll
        for (int q = 0; q < 8; q++) {
            int c = ch*32 + 4*q;
            float2 p0 = unpack2(a0[2*q]), p1 = unpack2(a0[2*q+1]);
            red4(&g_acc0[d0*64 + c], p0.x*sew[c], p0.y*sew[c+1], p1.x*sew[c+2], p1.y*sew[c+3]);
            float2 q0 = unpack2(a1[2*q]), q1 = unpack2(a1[2*q+1]);
            red4(&g_acc0[d1*64 + c], q0.x*sew[c], q0.y*sew[c+1], q1.x*sew[c+2], q1.y*sew[c+3]);
        }
    }
    // ---- stage 4: wd1 scatter (outer with Y1) ----
#pragma unroll 1
    for (int ch = 0; ch < 2; ch++) {
        initp16(a0, sbd + 64 + ch*32); initp16(a1, sbd + 64 + ch*32);
        gemv2g<128>(sWd + 64 + ch*32, g_hmid + e0, a0, a1);
#pragma unroll
        for (int q = 0; q < 8; q++) {
            int c = ch*32 + 4*q;
            float2 p0 = unpack2(a0[2*q]), p1 = unpack2(a0[2*q+1]);
            float w0 = p0.x*sew[c], w1 = p0.y*sew[c+1], w2 = p1.x*sew[c+2], w3 = p1.y*sew[c+3];
#pragma unroll
            for (int i = 0; i < 3; i++) {
                float yi = (i == 0) ? y00 : ((i == 1) ? y01 : y02);
                red4(&g_acc1[(size_t)d0*192 + i*64 + c], w0*yi, w1*yi, w2*yi, w3*yi);
            }
            float2 q0 = unpack2(a1[2*q]), q1 = unpack2(a1[2*q+1]);
            float u0 = q0.x*sew[c], u1 = q0.y*sew[c+1], u2 = q1.x*sew[c+2], u3 = q1.y*sew[c+3];
#pragma unroll
            for (int i = 0; i < 3; i++) {
                float yi = (i == 0) ? y10 : ((i == 1) ? y11 : y12);
                red4(&g_acc1[(size_t)d1*192 + i*64 + c], u0*yi, u1*yi, u2*yi, u3*yi);
            }
        }
    }
}

// ---------------- K2: node embed + deg proj ------------------------------
__global__ void __launch_bounds__(128) k_node_deg(
    const float* __restrict__ embed_W, const float* __restrict__ P0,
    const float* __restrict__ P1, const int* __restrict__ atom)
{
    extern __shared__ float sm[];
    float* sP0 = sm; float* sP1 = sP0 + 4096; float* sx = sP1 + 4096;
    for (int i = threadIdx.x; i < 4096; i += 128) { sP0[i] = P0[i]; sP1[i] = P1[i]; }
    __syncthreads();
    int tid = threadIdx.x;
    int n = blockIdx.x * 128 + tid;
    if (n >= NN) return;
    int at = atom[n];
    ull acc[32];
#pragma unroll
    for (int g = 0; g < 16; g++) { float4 v = ((const float4*)(g_acc0 + n*64))[g];
        sx[(4*g)*128+tid]=v.x; sx[(4*g+1)*128+tid]=v.y; sx[(4*g+2)*128+tid]=v.z; sx[(4*g+3)*128+tid]=v.w; }
    zerop(acc);
    gemv_s<8, 64, 128>(sP0, sx, tid, acc);
#pragma unroll
    for (int i = 0; i < 32; i++) { float2 v = unpack2(acc[i]);
        g_f0[n*64 + 2*i]   = embed_W[at*64 + 2*i]   + 0.25f * v.x;
        g_f0[n*64 + 2*i+1] = embed_W[at*64 + 2*i+1] + 0.25f * v.y; }
#pragma unroll 1
    for (int i = 0; i < 3; i++) {
#pragma unroll
        for (int g = 0; g < 16; g++) { float4 v = ((const float4*)(g_acc1 + (size_t)n*192 + i*64))[g];
            sx[(4*g)*128+tid]=v.x; sx[(4*g+1)*128+tid]=v.y; sx[(4*g+2)*128+tid]=v.z; sx[(4*g+3)*128+tid]=v.w; }
        zerop(acc);
        gemv_s<8, 64, 128>(sP1, sx, tid, acc);
#pragma unroll
        for (int j = 0; j < 32; j++) { float2 v = unpack2(acc[j]);
            g_f1[(size_t)n*192 + i*64 + 2*j]   = 0.25f * v.x;
            g_f1[(size_t)n*192 + i*64 + 2*j+1] = 0.25f * v.y; }
    }
}

// ---------------- K3: edge attention (adjacent pair, R9 structure) --------
__global__ void __launch_bounds__(256, 2) k_edge_attn(
    const float* __restrict__ Wattn, const float* __restrict__ battn,
    const float* __restrict__ alpha_dot,
    const int* __restrict__ esrc, const int* __restrict__ edst)
{
    extern __shared__ float sm[];
    float* sW  = sm;                // 20480
    float* sb  = sW + 20480;        // 320
    float* sad = sb + 320;          // 64
    for (int i = threadIdx.x; i < 20480; i += 256) sW[i] = Wattn[i];
    for (int i = threadIdx.x; i < 320; i += 256) sb[i] = battn[i];
    if (threadIdx.x < 64) sad[threadIdx.x] = alpha_dot[threadIdx.x];
    __syncthreads();

    int tid = threadIdx.x;
    int e0 = blockIdx.x * 512 + 2 * tid;
    if (e0 >= NE) return;
    int2 ss = *(const int2*)&esrc[e0];
    int2 dd = *(const int2*)&edst[e0];
    int s0 = ss.x, s1 = ss.y, d0 = dd.x, d1 = dd.y;
    float2 yv0 = *(const float2*)&g_Y1[e0];
    float2 yv1 = *(const float2*)&g_Y1[NE+e0];
    float2 yv2 = *(const float2*)&g_Y1[2*NE+e0];
    float y00 = yv0.x, y01 = yv1.x, y02 = yv2.x;
    float y10 = yv0.y, y11 = yv1.y, y12 = yv2.y;

    const float4* f0p0 = (const float4*)(g_f0 + (size_t)s0*64);
    const float4* f1p0 = (const float4*)(g_f1 + (size_t)s0*192);
    const float4* f0p1 = (const float4*)(g_f0 + (size_t)s1*64);
    const float4* f1p1 = (const float4*)(g_f1 + (size_t)s1*192);
    const float is3 = 0.5773502691896258f, is2 = 0.7071067811865476f;
    float hsum0 = 0.f, hsum1 = 0.f;

#pragma unroll 1
    for (int g = 0; g < 16; g++) {
        ull acc0[5][2], acc1[5][2];
#pragma unroll
        for (int q = 0; q < 5; q++) {
            ull b0 = *(const ull*)(sb + q*64 + 4*g);
            ull b1 = *(const ull*)(sb + q*64 + 4*g + 2);
            acc0[q][0] = b0; acc0[q][1] = b1;
            acc1[q][0] = b0; acc1[q][1] = b1;
        }
        float2 xc[8], xn[8];
#pragma unroll
        for (int i = 0; i < 8; i++) xc[i] = *(const float2*)(g_hmid + (size_t)i*NE + e0);
#pragma unroll 1
        for (int k0 = 0; k0 < 8; k0++) {
            if (k0 < 7) {
#pragma unroll
                for (int i = 0; i < 8; i++)
                    xn[i] = *(const float2*)(g_hmid + (size_t)((k0+1)*8 + i)*NE + e0);
            }
#pragma unroll
            for (int i = 0; i < 8; i++) {
                ull x0 = pack2(xc[i].x), x1 = pack2(xc[i].y);
                const float* wb = sW + (k0*8 + i)*320 + 4*g;
#pragma unroll
                for (int q = 0; q < 5; q++) {
                    ulonglong2 w = *(const ulonglong2*)(wb + q*64);
                    FMA2(acc0[q][0], x0, w.x); FMA2(acc0[q][1], x0, w.y);
                    FMA2(acc1[q][0], x1, w.x); FMA2(acc1[q][1], x1, w.y);
                }
            }
#pragma unroll
            for (int i = 0; i < 8; i++) xc[i] = xn[i];
        }
        // ---- epilogue (both edges) ----
        float wq0[5][4], wq1[5][4];
#pragma unroll
        for (int q = 0; q < 5; q++) {
            float2 a = unpack2(acc0[q][0]), b = unpack2(acc0[q][1]);
            wq0[q][0] = a.x; wq0[q][1] = a.y; wq0[q][2] = b.x; wq0[q][3] = b.y;
            float2 c = unpack2(acc1[q][0]), d = unpack2(acc1[q][1]);
            wq1[q][0] = c.x; wq1[q][1] = c.y; wq1[q][2] = d.x; wq1[q][3] = d.y;
        }
        float4 P00 = f0p0[g], Pa0 = f1p0[g], Pb0 = f1p0[16+g], Pc0 = f1p0[32+g];
        float4 P01 = f0p1[g], Pa1 = f1p1[g], Pb1 = f1p1[16+g], Pc1 = f1p1[32+g];
        float s0v0[4] = {P00.x,P00.y,P00.z,P00.w};
        float a0v0[4] = {Pa0.x,Pa0.y,Pa0.z,Pa0.w};
        float a1v0[4] = {Pb0.x,Pb0.y,Pb0.z,Pb0.w};
        float a2v0[4] = {Pc0.x,Pc0.y,Pc0.z,Pc0.w};
        float s0v1[4] = {P01.x,P01.y,P01.z,P01.w};
        float a0v1[4] = {Pa1.x,Pa1.y,Pa1.z,Pa1.w};
        float a1v1[4] = {Pb1.x,Pb1.y,Pb1.z,Pb1.w};
        float a2v1[4] = {Pc1.x,Pc1.y,Pc1.z,Pc1.w};
#pragma unroll
        for (int u = 0; u < 4; u++) {
            int c = 4*g + u;
            float m00, m10a, m11a, m12a;
            {
                float w0 = wq0[0][u], w1 = wq0[1][u], w2 = wq0[2][u], w3 = wq0[3][u], w4 = wq0[4][u];
                float s0c = s0v0[u], a0 = a0v0[u], a1 = a1v0[u], a2 = a2v0[u];
                float dot = a0*y00 + a1*y01 + a2*y02;
                m00 = w0*s0c + w3*dot*is3;
                float cx = a1*y02 - a2*y01, cy = a2*y00 - a0*y02, cz = a0*y01 - a1*y00;
                m10a = w1*s0c*y00 + w2*a0 + w4*cx*is2;
                m11a = w1*s0c*y01 + w2*a1 + w4*cy*is2;
                m12a = w1*s0c*y02 + w2*a2 + w4*cz*is2;
                hsum0 += (0.2f*m00 + 0.8f*m00*sigf(m00)) * sad[c];
            }
            float m01, m10b, m11b, m12b;
            {
                float w0 = wq1[0][u], w1 = wq1[1][u], w2 = wq1[2][u], w3 = wq1[3][u], w4 = wq1[4][u];
                float s0c = s0v1[u], a0 = a0v1[u], a1 = a1v1[u], a2 = a2v1[u];
                float dot = a0*y10 + a1*y11 + a2*y12;
                m01 = w0*s0c + w3*dot*is3;
                float cx = a1*y12 - a2*y11, cy = a2*y10 - a0*y12, cz = a0*y11 - a1*y10;
                m10b = w1*s0c*y10 + w2*a0 + w4*cx*is2;
                m11b = w1*s0c*y11 + w2*a1 + w4*cy*is2;
                m12b = w1*s0c*y12 + w2*a2 + w4*cz*is2;
                hsum1 += (0.2f*m01 + 0.8f*m01*sigf(m01)) * sad[c];
            }
            *(float2*)&g_msg0[(size_t)c*NE + e0]          = make_float2(m00, m01);
            *(float2*)&g_msg1[(size_t)(0*64+c)*NE + e0]   = make_float2(m10a, m10b);
            *(float2*)&g_msg1[(size_t)(1*64+c)*NE + e0]   = make_float2(m11a, m11b);
            *(float2*)&g_msg1[(size_t)(2*64+c)*NE + e0]   = make_float2(m12a, m12b);
        }
        if (g & 1) {
            int hh = g >> 1;
            *(float2*)&g_a[(size_t)hh*NE + e0] = make_float2(hsum0, hsum1);
            atomicMax(&g_amax[d0*8 + hh], fkey(hsum0));
            atomicMax(&g_amax[d1*8 + hh], fkey(hsum1));
            hsum0 = 0.f; hsum1 = 0.f;
        }
    }
}

// ---------------- K4: ea + z scatter + aggregation (fused, 2 edges) ------
__global__ void __launch_bounds__(256) k_edge_agg(const int* __restrict__ edst) {
    int tid = threadIdx.x;
    int e0 = blockIdx.x * 512 + 2 * tid;
    if (e0 >= NE) return;
    int2 dd = *(const int2*)&edst[e0];
    int d0 = dd.x, d1 = dd.y;
    float2 ea[8];
#pragma unroll
    for (int h = 0; h < 8; h++) {
        float2 a = *(const float2*)&g_a[(size_t)h*NE + e0];
        ea[h].x = __expf(a.x - fdec(g_amax[d0*8 + h]));
        ea[h].y = __expf(a.y - fdec(g_amax[d1*8 + h]));
    }
    red4(&g_z[d0*8],     ea[0].x, ea[1].x, ea[2].x, ea[3].x);
    red4(&g_z[d0*8 + 4], ea[4].x, ea[5].x, ea[6].x, ea[7].x);
    red4(&g_z[d1*8],     ea[0].y, ea[1].y, ea[2].y, ea[3].y);
    red4(&g_z[d1*8 + 4], ea[4].y, ea[5].y, ea[6].y, ea[7].y);
#pragma unroll
    for (int g = 0; g < 16; g++) {
        float2 w = ea[g >> 1];
        float2 m0 = *(const float2*)&g_msg0[(size_t)(4*g)*NE + e0];
        float2 m1 = *(const float2*)&g_msg0[(size_t)(4*g+1)*NE + e0];
        float2 m2 = *(const float2*)&g_msg0[(size_t)(4*g+2)*NE + e0];
        float2 m3 = *(const float2*)&g_msg0[(size_t)(4*g+3)*NE + e0];
        red4(&g_agg0[d0*64 + 4*g], m0.x*w.x, m1.x*w.x, m2.x*w.x, m3.x*w.x);
        red4(&g_agg0[d1*64 + 4*g], m0.y*w.y, m1.y*w.y, m2.y*w.y, m3.y*w.y);
#pragma unroll
        for (int i = 0; i < 3; i++) {
            float2 u0 = *(const float2*)&g_msg1[(size_t)(i*64 + 4*g)*NE + e0];
            float2 u1 = *(const float2*)&g_msg1[(size_t)(i*64 + 4*g+1)*NE + e0];
            float2 u2 = *(const float2*)&g_msg1[(size_t)(i*64 + 4*g+2)*NE + e0];
            float2 u3 = *(const float2*)&g_msg1[(size_t)(i*64 + 4*g+3)*NE + e0];
            red4(&g_agg1[(size_t)d0*192 + i*64 + 4*g], u0.x*w.x, u1.x*w.x, u2.x*w.x, u3.x*w.x);
            red4(&g_agg1[(size_t)d1*192 + i*64 + 4*g], u0.y*w.y, u1.y*w.y, u2.y*w.y, u3.y*w.y);
        }
    }
}

// ---------------- K6: node out_proj + FFN part A -------------------------
__global__ void __launch_bounds__(128) k_node_postA(
    const float* __restrict__ P0, const float* __restrict__ P1,
    const float* __restrict__ W1s, const float* __restrict__ b1s)
{
    extern __shared__ float sm[];
    float* sP0 = sm; float* sP1 = sP0 + 4096; float* sWs = sP1 + 4096;
    float* sbs = sWs + 8192; float* sx = sbs + 128;
    for (int i = threadIdx.x; i < 4096; i += 128) { sP0[i] = P0[i]; sP1[i] = P1[i]; }
    for (int i = threadIdx.x; i < 8192; i += 128) sWs[i] = W1s[i];
    if (threadIdx.x < 128) sbs[threadIdx.x] = b1s[threadIdx.x];
    __syncthreads();
    int tid = threadIdx.x;
    int n = blockIdx.x * 128 + tid;
    if (n >= NN) return;
    float rz[8];
#pragma unroll
    for (int h = 0; h < 8; h++) {
        float z = g_z[n*8 + h];
        rz[h] = (z > 0.f) ? __fdividef(1.f, z) : 0.f;
    }
    ull acc[32];
#pragma unroll
    for (int g = 0; g < 16; g++) { float4 v = ((const float4*)(g_agg0 + n*64))[g];
        float r = rz[g >> 1];
        sx[(4*g)*128+tid]=v.x*r; sx[(4*g+1)*128+tid]=v.y*r;
        sx[(4*g+2)*128+tid]=v.z*r; sx[(4*g+3)*128+tid]=v.w*r; }
    zerop(acc);
    gemv_s<8, 64, 128>(sP0, sx, tid, acc);
    float x[64];
#pragma unroll
    for (int i = 0; i < 32; i++) { float2 v = unpack2(acc[i]);
        float a = g_f0[n*64 + 2*i] + v.x, b = g_f0[n*64 + 2*i+1] + v.y;
        x[2*i] = a; x[2*i+1] = b;
        g_f0[n*64 + 2*i] = a; g_f0[n*64 + 2*i+1] = b;
        sx[(2*i)*128+tid] = a; sx[(2*i+1)*128+tid] = b; }
    zerop(acc);
    gemv_s<8, 128, 128>(sWs, sx, tid, acc);
#pragma unroll
    for (int i = 0; i < 32; i++) { float2 v = unpack2(acc[i]);
        g_mid[n*64 + 2*i]   = siluf(v.x + sbs[2*i]);
        g_mid[n*64 + 2*i+1] = siluf(v.y + sbs[2*i+1]); }
    zerop(acc);
    gemv_s<8, 128, 128>(sWs + 64, sx, tid, acc);
#pragma unroll
    for (int i = 0; i < 32; i++) { float2 v = unpack2(acc[i]);
        g_gateT[(size_t)(2*i)*NN + n]   = sigf(v.x + sbs[64 + 2*i]);
        g_gateT[(size_t)(2*i+1)*NN + n] = sigf(v.y + sbs[64 + 2*i+1]); }
#pragma unroll 1
    for (int i = 0; i < 3; i++) {
#pragma unroll
        for (int g = 0; g < 16; g++) { float4 v = ((const float4*)(g_agg1 + (size_t)n*192 + i*64))[g];
            float r = rz[g >> 1];
            sx[(4*g)*128+tid]=v.x*r; sx[(4*g+1)*128+tid]=v.y*r;
            sx[(4*g+2)*128+tid]=v.z*r; sx[(4*g+3)*128+tid]=v.w*r; }
        zerop(acc);
        gemv_s<8, 64, 128>(sP1, sx, tid, acc);
#pragma unroll
        for (int j = 0; j < 32; j++) { float2 v = unpack2(acc[j]);
            g_f1[(size_t)n*192 + i*64 + 2*j]   += v.x;
            g_f1[(size_t)n*192 + i*64 + 2*j+1] += v.y; }
    }
}

// ---------------- K7: node FFN part B + output ---------------------------
__global__ void __launch_bounds__(128) k_node_postB(
    const float* __restrict__ W2s, const float* __restrict__ b2s,
    const float* __restrict__ W1v, const float* __restrict__ W2v,
    float* __restrict__ out)
{
    extern __shared__ float sm[];
    float* sWs = sm; float* sWa = sWs + 4096; float* sWb = sWa + 4096;
    float* sb2 = sWb + 4096; float* sx = sb2 + 64;
    for (int i = threadIdx.x; i < 4096; i += 128) { sWs[i] = W2s[i]; sWa[i] = W1v[i]; sWb[i] = W2v[i]; }
    if (threadIdx.x < 64) sb2[threadIdx.x] = b2s[threadIdx.x];
    __syncthreads();
    int tid = threadIdx.x;
    int n = blockIdx.x * 128 + tid;
    if (n >= NN) return;
    ull acc[32];
#pragma unroll
    for (int g = 0; g < 16; g++) { float4 v = ((const float4*)(g_mid + n*64))[g];
        sx[(4*g)*128+tid]=v.x; sx[(4*g+1)*128+tid]=v.y;
        sx[(4*g+2)*128+tid]=v.z; sx[(4*g+3)*128+tid]=v.w; }
    zerop(acc);
    gemv_s<8, 64, 128>(sWs, sx, tid, acc);
#pragma unroll
    for (int i = 0; i < 32; i++) { float2 v = unpack2(acc[i]);
        out[(size_t)n*256 + 2*i]   = g_f0[n*64 + 2*i]   + v.x + sb2[2*i];
        out[(size_t)n*256 + 2*i+1] = g_f0[n*64 + 2*i+1] + v.y + sb2[2*i+1]; }

    float gate[64];
#pragma unroll
    for (int j = 0; j < 64; j++) gate[j] = g_gateT[(size_t)j*NN + n];
#pragma unroll 1
    for (int i = 0; i < 3; i++) {
        float x[64];
#pragma unroll
        for (int g = 0; g < 16; g++) { float4 v = ((const float4*)(g_f1 + (size_t)n*192 + i*64))[g];
            x[4*g]=v.x; x[4*g+1]=v.y; x[4*g+2]=v.z; x[4*g+3]=v.w;
            sx[(4*g)*128+tid]=v.x; sx[(4*g+1)*128+tid]=v.y;
            sx[(4*g+2)*128+tid]=v.z; sx[(4*g+3)*128+tid]=v.w; }
        zerop(acc);
        gemv_s<8, 64, 128>(sWa, sx, tid, acc);
#pragma unroll
        for (int j = 0; j < 32; j++) { float2 v = unpack2(acc[j]);
            sx[(2*j)*128+tid]   = v.x * gate[2*j];
            sx[(2*j+1)*128+tid] = v.y * gate[2*j+1]; }
        zerop(acc);
        gemv_s<8, 64, 128>(sWb, sx, tid, acc);
#pragma unroll
        for (int j = 0; j < 32; j++) { float2 v = unpack2(acc[j]);
            out[(size_t)n*256 + 64 + (2*j)*3 + i]   = x[2*j]   + v.x;
            out[(size_t)n*256 + 64 + (2*j+1)*3 + i] = x[2*j+1] + v.y; }
    }
}

// ---------------- launch -------------------------------------------------
extern "C" void kernel_launch(void* const* d_in, const int* in_sizes, int n_in,
                              void* d_out, int out_size) {
    const float* pos     = (const float*)d_in[0];
    const float* embed_W = (const float*)d_in[1];
    const float* exp_w   = (const float*)d_in[2];
    const float* rW1     = (const float*)d_in[3];
    const float* rb1     = (const float*)d_in[4];
    const float* rW2     = (const float*)d_in[5];
    const float* rb2     = (const float*)d_in[6];
    const float* rWdeg   = (const float*)d_in[7];
    const float* rbdeg   = (const float*)d_in[8];
    const float* rWattn  = (const float*)d_in[9];
    const float* rbattn  = (const float*)d_in[10];
    const float* dp0     = (const float*)d_in[11];
    const float* dp1     = (const float*)d_in[12];
    const float* adot    = (const float*)d_in[13];
    const float* op0     = (const float*)d_in[14];
    const float* op1     = (const float*)d_in[15];
    const float* fW1s    = (const float*)d_in[16];
    const float* fb1s    = (const float*)d_in[17];
    const float* fW1v    = (const float*)d_in[18];
    const float* fW2s    = (const float*)d_in[19];
    const float* fb2s    = (const float*)d_in[20];
    const float* fW2v    = (const float*)d_in[21];
    const int*   atom    = (const int*)d_in[22];
    const int*   esrc    = (const int*)d_in[23];
    const int*   edst    = (const int*)d_in[24];
    float* out = (float*)d_out;

    const int SM_DEG = (3584 + 4096 + 8192 + 64 + 64 + 128 + 64) * 4;
    const int SM_ATT = (20480 + 320 + 64) * 4;
    const int SM_ND  = (4096 + 4096 + 64*128) * 4;
    const int SM_PA  = (4096 + 4096 + 8192 + 128 + 64*128) * 4;
    const int SM_PB  = (4096*3 + 64 + 64*128) * 4;
    cudaFuncSetAttribute(k_edge_deg,   cudaFuncAttributeMaxDynamicSharedMemorySize, SM_DEG);
    cudaFuncSetAttribute(k_edge_attn,  cudaFuncAttributeMaxDynamicSharedMemorySize, SM_ATT);
    cudaFuncSetAttribute(k_node_deg,   cudaFuncAttributeMaxDynamicSharedMemorySize, SM_ND);
    cudaFuncSetAttribute(k_node_postA, cudaFuncAttributeMaxDynamicSharedMemorySize, SM_PA);
    cudaFuncSetAttribute(k_node_postB, cudaFuncAttributeMaxDynamicSharedMemorySize, SM_PB);

    int eb2 = (NE + 511) / 512;
    int nb  = (NN + 127) / 128;
    k_zero<<<592, 256>>>();
    k_edge_deg<<<eb2, 256, SM_DEG>>>(pos, exp_w, rW1, rb1, rW2, rb2, rWdeg, rbdeg, esrc, edst);
    k_node_deg<<<nb, 128, SM_ND>>>(embed_W, dp0, dp1, atom);
    k_edge_attn<<<eb2, 256, SM_ATT>>>(rWattn, rbattn, adot, esrc, edst);
    k_edge_agg<<<eb2, 256>>>(edst);
    k_node_postA<<<nb, 128, SM_PA>>>(op0, op1, fW1s, fb1s);
    k_node_postB<<<nb, 128, SM_PB>>>(fW2s, fb2s, fW1v, fW2v, out);
}